// round 1
// baseline (speedup 1.0000x reference)
#include <cuda_runtime.h>

// ---------------------------------------------------------------------------
// RSAGE_Hetero: 2-layer hetero GraphSAGE, restructured:
//   - transform-before-aggregate (mean is linear)
//   - fused self-term weights: Wc = 0.5*(Wr[0]+Wr[1])
//   - CSR build per launch, warp-per-node gather (no float atomics)
//   - layer-2 author branch skipped (dead output)
// ---------------------------------------------------------------------------

constexpr int NPn  = 50000;
constexpr int NAn  = 20000;
constexpr int DIN  = 128;
constexpr int DH   = 128;
constexpr int DOUT = 64;
constexpr int EWn  = 250000;
constexpr int ECn  = 500000;
constexpr int ERn  = 250000;

// ------------------------------ scratch ------------------------------------
__device__ float g_ya[NAn * DH];
__device__ float g_yp[NPn * DH];
__device__ float g_yr[NPn * DH];
__device__ float g_aggP[NPn * DH];
__device__ float g_aggA[NAn * DH];
__device__ float g_hp1[NPn * DH];
__device__ float g_ha1[NAn * DH];
__device__ float g_za[NAn * DOUT];
__device__ float g_zp[NPn * DOUT];
__device__ float g_aggP2[NPn * DOUT];

__device__ int g_degW[NPn], g_degC[NPn], g_degA[NAn];
__device__ int g_offW[NPn + 1], g_offC[NPn + 1], g_offA[NAn + 1];
__device__ int g_curW[NPn], g_curC[NPn], g_curA[NAn];
__device__ int g_srcW[EWn], g_srcC[ECn], g_srcA[ERn];

__device__ float g_Wc1[DH * DIN];
__device__ float g_bc1[DH];
__device__ float g_Wc2[DOUT * DH];
__device__ float g_bc2[DOUT];

// --------------------------- CSR construction ------------------------------
__global__ void zero_deg_kernel() {
    int i = blockIdx.x * blockDim.x + threadIdx.x;
    if (i < NPn) { g_degW[i] = 0; g_degC[i] = 0; }
    if (i < NAn) { g_degA[i] = 0; }
}

__global__ void hist_all_kernel(const int* __restrict__ wdst,
                                const int* __restrict__ cdst,
                                const int* __restrict__ rdst) {
    const int T = EWn + ECn + ERn;
    for (int i = blockIdx.x * blockDim.x + threadIdx.x; i < T;
         i += gridDim.x * blockDim.x) {
        if (i < EWn)              atomicAdd(&g_degW[wdst[i]], 1);
        else if (i < EWn + ECn)   atomicAdd(&g_degC[cdst[i - EWn]], 1);
        else                      atomicAdd(&g_degA[rdst[i - EWn - ECn]], 1);
    }
}

// 3 blocks, one per relation: exclusive scan deg -> off, cur; off[n]=total
__global__ void __launch_bounds__(1024) exscan3_kernel() {
    const int* deg; int* off; int* cur; int n;
    if (blockIdx.x == 0)      { deg = g_degW; off = g_offW; cur = g_curW; n = NPn; }
    else if (blockIdx.x == 1) { deg = g_degC; off = g_offC; cur = g_curC; n = NPn; }
    else                      { deg = g_degA; off = g_offA; cur = g_curA; n = NAn; }

    __shared__ int s[1024];
    const int tid = threadIdx.x;
    const int chunk = (n + 1023) / 1024;
    int lo = tid * chunk;
    int hi = lo + chunk; if (hi > n) hi = n; if (lo > n) lo = n;

    int sum = 0;
    for (int i = lo; i < hi; i++) sum += deg[i];
    s[tid] = sum;
    __syncthreads();

    #pragma unroll
    for (int d = 1; d < 1024; d <<= 1) {
        int v = (tid >= d) ? s[tid - d] : 0;
        __syncthreads();
        s[tid] += v;
        __syncthreads();
    }
    int run = s[tid] - sum;  // exclusive prefix for this chunk
    for (int i = lo; i < hi; i++) {
        off[i] = run;
        cur[i] = run;
        run += deg[i];
    }
    if (tid == 1023) off[n] = s[1023];
}

__global__ void fill_all_kernel(const int* __restrict__ wsrc, const int* __restrict__ wdst,
                                const int* __restrict__ csrc, const int* __restrict__ cdst,
                                const int* __restrict__ rsrc, const int* __restrict__ rdst) {
    const int T = EWn + ECn + ERn;
    for (int i = blockIdx.x * blockDim.x + threadIdx.x; i < T;
         i += gridDim.x * blockDim.x) {
        if (i < EWn) {
            int d = wdst[i];
            int p = atomicAdd(&g_curW[d], 1);
            g_srcW[p] = wsrc[i];
        } else if (i < EWn + ECn) {
            int j = i - EWn;
            int d = cdst[j];
            int p = atomicAdd(&g_curC[d], 1);
            g_srcC[p] = csrc[j];
        } else {
            int j = i - EWn - ECn;
            int d = rdst[j];
            int p = atomicAdd(&g_curA[d], 1);
            g_srcA[p] = rsrc[j];
        }
    }
}

// --------------------------- derived weights --------------------------------
__global__ void prep_weights_kernel(const float* __restrict__ Wr1,
                                    const float* __restrict__ bl1,
                                    const float* __restrict__ Wr2,
                                    const float* __restrict__ bl2) {
    int i = blockIdx.x * blockDim.x + threadIdx.x;
    if (i < DH * DIN)  g_Wc1[i] = 0.5f * (Wr1[i] + Wr1[DH * DIN + i]);
    if (i < DH)        g_bc1[i] = 0.5f * (bl1[i] + bl1[DH + i]);
    if (i < DOUT * DH) g_Wc2[i] = 0.5f * (Wr2[i] + Wr2[DOUT * DH + i]);
    if (i < DOUT)      g_bc2[i] = 0.5f * (bl2[i] + bl2[DOUT + i]);
}

// ------------------------------- GEMM ---------------------------------------
// C[M,BN] = act( alpha * A[M,128] @ W[BN,128]^T + bias + agg )
template <int BN>
__global__ void __launch_bounds__(256, 1)
gemm_k128(const float* __restrict__ A, const float* __restrict__ W,
          float* __restrict__ C, int M, float alpha,
          const float* __restrict__ bias, const float* __restrict__ agg,
          int do_relu) {
    constexpr int BM = 128, K = 128, PAD = 4;
    constexpr int NR = BN / 16;  // cols per thread (8 for BN=128, 4 for BN=64)
    extern __shared__ float sm[];
    float* sA = sm;                       // [K][BM+PAD], k-major
    float* sW = sm + K * (BM + PAD);      // [K][BN+PAD], k-major

    const int tid = threadIdx.x;
    const int m0 = blockIdx.x * BM;

    {   // load tiles (transposed into k-major layout)
        const int kc = tid & 31;      // float4 index along K
        const int r0 = tid >> 5;      // 0..7
        for (int r = r0; r < BM; r += 8) {
            const int gm = m0 + r;
            float4 v = make_float4(0.f, 0.f, 0.f, 0.f);
            if (gm < M) v = *(const float4*)(A + (size_t)gm * K + kc * 4);
            sA[(kc * 4 + 0) * (BM + PAD) + r] = v.x;
            sA[(kc * 4 + 1) * (BM + PAD) + r] = v.y;
            sA[(kc * 4 + 2) * (BM + PAD) + r] = v.z;
            sA[(kc * 4 + 3) * (BM + PAD) + r] = v.w;
        }
        for (int r = r0; r < BN; r += 8) {
            float4 v = *(const float4*)(W + (size_t)r * K + kc * 4);
            sW[(kc * 4 + 0) * (BN + PAD) + r] = v.x;
            sW[(kc * 4 + 1) * (BN + PAD) + r] = v.y;
            sW[(kc * 4 + 2) * (BN + PAD) + r] = v.z;
            sW[(kc * 4 + 3) * (BN + PAD) + r] = v.w;
        }
    }
    __syncthreads();

    const int tx = tid & 15, ty = tid >> 4;
    const int rb = ty * 8, cb = tx * NR;

    float acc[8][NR];
    #pragma unroll
    for (int i = 0; i < 8; i++)
        #pragma unroll
        for (int j = 0; j < NR; j++) acc[i][j] = 0.f;

    #pragma unroll 8
    for (int kk = 0; kk < K; kk++) {
        float a[8], w[NR];
        float4 a0 = *(const float4*)&sA[kk * (BM + PAD) + rb];
        float4 a1 = *(const float4*)&sA[kk * (BM + PAD) + rb + 4];
        a[0] = a0.x; a[1] = a0.y; a[2] = a0.z; a[3] = a0.w;
        a[4] = a1.x; a[5] = a1.y; a[6] = a1.z; a[7] = a1.w;
        float4 w0 = *(const float4*)&sW[kk * (BN + PAD) + cb];
        w[0] = w0.x; w[1] = w0.y; w[2] = w0.z; w[3] = w0.w;
        if (NR == 8) {
            float4 w1 = *(const float4*)&sW[kk * (BN + PAD) + cb + 4];
            w[4] = w1.x; w[5] = w1.y; w[6] = w1.z; w[7] = w1.w;
        }
        #pragma unroll
        for (int i = 0; i < 8; i++)
            #pragma unroll
            for (int j = 0; j < NR; j++)
                acc[i][j] = fmaf(a[i], w[j], acc[i][j]);
    }

    #pragma unroll
    for (int i = 0; i < 8; i++) {
        const int gm = m0 + rb + i;
        if (gm >= M) break;
        #pragma unroll
        for (int j = 0; j < NR; j++) {
            const int c = cb + j;
            float v = alpha * acc[i][j];
            if (bias) v += bias[c];
            if (agg)  v += agg[(size_t)gm * BN + c];
            if (do_relu) v = fmaxf(v, 0.f);
            C[(size_t)gm * BN + c] = v;
        }
    }
}

// ------------------------------ gather --------------------------------------
// out[node] = sum(y1[src1]) / max(deg1,1)  (+ same for relation 2 if present)
// One warp per dst node; VEC floats per lane (D = 32*VEC).
template <int VEC>
__global__ void gather_kernel(const int* __restrict__ off1, const int* __restrict__ src1,
                              const float* __restrict__ y1,
                              const int* __restrict__ off2, const int* __restrict__ src2,
                              const float* __restrict__ y2,
                              float* __restrict__ out, int n) {
    const int wid  = (blockIdx.x * blockDim.x + threadIdx.x) >> 5;
    const int lane = threadIdx.x & 31;
    if (wid >= n) return;
    constexpr int D = 32 * VEC;

    float res[VEC];
    #pragma unroll
    for (int v = 0; v < VEC; v++) res[v] = 0.f;

    const int* offs[2] = {off1, off2};
    const int* srcs[2] = {src1, src2};
    const float* ys[2] = {y1, y2};

    #pragma unroll
    for (int rel = 0; rel < 2; rel++) {
        if (!offs[rel]) break;
        const int b = offs[rel][wid];
        const int e = offs[rel][wid + 1];
        float acc[VEC];
        #pragma unroll
        for (int v = 0; v < VEC; v++) acc[v] = 0.f;

        int i = b;
        for (; i + 1 < e; i += 2) {   // 2-deep MLP
            const int s0 = __ldg(&srcs[rel][i]);
            const int s1 = __ldg(&srcs[rel][i + 1]);
            const float* r0 = ys[rel] + (size_t)s0 * D + lane * VEC;
            const float* r1 = ys[rel] + (size_t)s1 * D + lane * VEC;
            if (VEC == 4) {
                float4 t0 = *(const float4*)r0;
                float4 t1 = *(const float4*)r1;
                acc[0] += t0.x + t1.x; acc[1] += t0.y + t1.y;
                acc[2] += t0.z + t1.z; acc[3] += t0.w + t1.w;
            } else {
                float2 t0 = *(const float2*)r0;
                float2 t1 = *(const float2*)r1;
                acc[0] += t0.x + t1.x; acc[1] += t0.y + t1.y;
            }
        }
        if (i < e) {
            const int s0 = __ldg(&srcs[rel][i]);
            const float* r0 = ys[rel] + (size_t)s0 * D + lane * VEC;
            if (VEC == 4) {
                float4 t0 = *(const float4*)r0;
                acc[0] += t0.x; acc[1] += t0.y; acc[2] += t0.z; acc[3] += t0.w;
            } else {
                float2 t0 = *(const float2*)r0;
                acc[0] += t0.x; acc[1] += t0.y;
            }
        }
        const int deg = e - b;
        const float inv = deg > 0 ? 1.f / (float)deg : 0.f;
        #pragma unroll
        for (int v = 0; v < VEC; v++) res[v] += acc[v] * inv;
    }

    float* o = out + (size_t)wid * D + lane * VEC;
    if (VEC == 4) *(float4*)o = make_float4(res[0], res[1], res[2], res[3]);
    else          *(float2*)o = make_float2(res[0], res[1]);
}

// ------------------------------- launch -------------------------------------
extern "C" void kernel_launch(void* const* d_in, const int* in_sizes, int n_in,
                              void* d_out, int out_size) {
    const float* xp  = (const float*)d_in[0];
    const float* xa  = (const float*)d_in[1];
    const float* Wl1 = (const float*)d_in[2];
    const float* bl1 = (const float*)d_in[3];
    const float* Wr1 = (const float*)d_in[4];
    const float* Wl2 = (const float*)d_in[5];
    const float* bl2 = (const float*)d_in[6];
    const float* Wr2 = (const float*)d_in[7];
    const int* wsrc = (const int*)d_in[8];
    const int* wdst = (const int*)d_in[9];
    const int* csrc = (const int*)d_in[10];
    const int* cdst = (const int*)d_in[11];
    const int* rsrc = (const int*)d_in[12];
    const int* rdst = (const int*)d_in[13];
    float* out = (float*)d_out;

    // resolve scratch symbol addresses (host query, not a stream op)
    float *p_ya, *p_yp, *p_yr, *p_aggP, *p_aggA, *p_hp1, *p_ha1, *p_za, *p_zp,
          *p_aggP2, *p_Wc1, *p_bc1, *p_Wc2, *p_bc2;
    int *p_offW, *p_offC, *p_offA, *p_srcW, *p_srcC, *p_srcA;
    cudaGetSymbolAddress((void**)&p_ya, g_ya);
    cudaGetSymbolAddress((void**)&p_yp, g_yp);
    cudaGetSymbolAddress((void**)&p_yr, g_yr);
    cudaGetSymbolAddress((void**)&p_aggP, g_aggP);
    cudaGetSymbolAddress((void**)&p_aggA, g_aggA);
    cudaGetSymbolAddress((void**)&p_hp1, g_hp1);
    cudaGetSymbolAddress((void**)&p_ha1, g_ha1);
    cudaGetSymbolAddress((void**)&p_za, g_za);
    cudaGetSymbolAddress((void**)&p_zp, g_zp);
    cudaGetSymbolAddress((void**)&p_aggP2, g_aggP2);
    cudaGetSymbolAddress((void**)&p_Wc1, g_Wc1);
    cudaGetSymbolAddress((void**)&p_bc1, g_bc1);
    cudaGetSymbolAddress((void**)&p_Wc2, g_Wc2);
    cudaGetSymbolAddress((void**)&p_bc2, g_bc2);
    cudaGetSymbolAddress((void**)&p_offW, g_offW);
    cudaGetSymbolAddress((void**)&p_offC, g_offC);
    cudaGetSymbolAddress((void**)&p_offA, g_offA);
    cudaGetSymbolAddress((void**)&p_srcW, g_srcW);
    cudaGetSymbolAddress((void**)&p_srcC, g_srcC);
    cudaGetSymbolAddress((void**)&p_srcA, g_srcA);

    constexpr int SMEM128 = (128 * 132 + 128 * 132) * 4;  // 135168
    constexpr int SMEM64  = (128 * 132 + 128 * 68) * 4;   // 102400
    cudaFuncSetAttribute(gemm_k128<128>, cudaFuncAttributeMaxDynamicSharedMemorySize, SMEM128);
    cudaFuncSetAttribute(gemm_k128<64>,  cudaFuncAttributeMaxDynamicSharedMemorySize, SMEM64);

    // ---- CSR build (shared by both layers) ----
    zero_deg_kernel<<<(NPn + 255) / 256, 256>>>();
    hist_all_kernel<<<1024, 256>>>(wdst, cdst, rdst);
    exscan3_kernel<<<3, 1024>>>();
    fill_all_kernel<<<1024, 256>>>(wsrc, wdst, csrc, cdst, rsrc, rdst);

    prep_weights_kernel<<<(DH * DIN + 255) / 256, 256>>>(Wr1, bl1, Wr2, bl2);

    const int gNP = (NPn + 127) / 128;   // 391
    const int gNA = (NAn + 127) / 128;   // 157
    const int gwP = (NPn * 32 + 255) / 256;
    const int gwA = (NAn * 32 + 255) / 256;

    // ---- Layer 1 ----
    // transform-first (0.5 folded into writes/cites transforms)
    gemm_k128<128><<<gNA, 256, SMEM128>>>(xa, Wl1 + 0 * DH * DIN, p_ya, NAn, 0.5f, nullptr, nullptr, 0);
    gemm_k128<128><<<gNP, 256, SMEM128>>>(xp, Wl1 + 1 * DH * DIN, p_yp, NPn, 0.5f, nullptr, nullptr, 0);
    gemm_k128<128><<<gNP, 256, SMEM128>>>(xp, Wl1 + 2 * DH * DIN, p_yr, NPn, 1.0f, nullptr, nullptr, 0);

    gather_kernel<4><<<gwP, 256>>>(p_offW, p_srcW, p_ya, p_offC, p_srcC, p_yp, p_aggP, NPn);
    gather_kernel<4><<<gwA, 256>>>(p_offA, p_srcA, p_yr, nullptr, nullptr, nullptr, p_aggA, NAn);

    gemm_k128<128><<<gNP, 256, SMEM128>>>(xp, p_Wc1, p_hp1, NPn, 1.0f, p_bc1, p_aggP, 1);
    gemm_k128<128><<<gNA, 256, SMEM128>>>(xa, Wr1 + 2 * DH * DIN, p_ha1, NAn, 1.0f, bl1 + 2 * DH, p_aggA, 1);

    // ---- Layer 2 (papers only; author output is dead) ----
    gemm_k128<64><<<gNA, 256, SMEM64>>>(p_ha1, Wl2 + 0 * DOUT * DH, p_za, NAn, 0.5f, nullptr, nullptr, 0);
    gemm_k128<64><<<gNP, 256, SMEM64>>>(p_hp1, Wl2 + 1 * DOUT * DH, p_zp, NPn, 0.5f, nullptr, nullptr, 0);

    gather_kernel<2><<<gwP, 256>>>(p_offW, p_srcW, p_za, p_offC, p_srcC, p_zp, p_aggP2, NPn);

    gemm_k128<64><<<gNP, 256, SMEM64>>>(p_hp1, p_Wc2, out, NPn, 1.0f, p_bc2, p_aggP2, 0);
}

// round 4
// speedup vs baseline: 1.7513x; 1.7513x over previous
#include <cuda_runtime.h>
#include <cuda_bf16.h>
#include <cstdint>

// ---------------------------------------------------------------------------
// RSAGE_Hetero round 3: GEMMs on tensor cores via mma.sync bf16 (HMMA),
// 3-term split precision (Ahi*Whi + Alo*Whi + Ahi*Wlo, fp32 accum).
// tcgen05 is unavailable: harness PTX targets compute_103 (no 'a').
// Graph part (CSR build + warp gathers) unchanged from round 1.
// ---------------------------------------------------------------------------

constexpr int NPn  = 50000;
constexpr int NAn  = 20000;
constexpr int DIN  = 128;
constexpr int DH   = 128;
constexpr int DOUT = 64;
constexpr int EWn  = 250000;
constexpr int ECn  = 500000;
constexpr int ERn  = 250000;

// ------------------------------ scratch ------------------------------------
__device__ float g_ya[NAn * DH];
__device__ float g_yp[NPn * DH];
__device__ float g_yr[NPn * DH];
__device__ float g_aggP[NPn * DH];
__device__ float g_aggA[NAn * DH];
__device__ float g_hp1[NPn * DH];
__device__ float g_ha1[NAn * DH];
__device__ float g_za[NAn * DOUT];
__device__ float g_zp[NPn * DOUT];
__device__ float g_aggP2[NPn * DOUT];

__device__ int g_degW[NPn], g_degC[NPn], g_degA[NAn];
__device__ int g_offW[NPn + 1], g_offC[NPn + 1], g_offA[NAn + 1];
__device__ int g_curW[NPn], g_curC[NPn], g_curA[NAn];
__device__ int g_srcW[EWn], g_srcC[ECn], g_srcA[ERn];

__device__ float g_Wc1[DH * DIN];
__device__ float g_bc1[DH];
__device__ float g_Wc2[DOUT * DH];
__device__ float g_bc2[DOUT];

// --------------------------- PTX helpers -----------------------------------
__device__ __forceinline__ uint32_t smem_u32(const void* p) {
    uint32_t a;
    asm("{ .reg .u64 t; cvta.to.shared.u64 t, %1; cvt.u32.u64 %0, t; }"
        : "=r"(a) : "l"(p));
    return a;
}

__device__ __forceinline__ void ldmx4(uint32_t* r, uint32_t addr) {
    asm volatile(
        "ldmatrix.sync.aligned.m8n8.x4.shared.b16 {%0,%1,%2,%3}, [%4];"
        : "=r"(r[0]), "=r"(r[1]), "=r"(r[2]), "=r"(r[3]) : "r"(addr));
}

__device__ __forceinline__ void mma16816(float* c, const uint32_t* a,
                                         uint32_t b0, uint32_t b1) {
    asm volatile(
        "mma.sync.aligned.m16n8k16.row.col.f32.bf16.bf16.f32 "
        "{%0,%1,%2,%3}, {%4,%5,%6,%7}, {%8,%9}, {%0,%1,%2,%3};"
        : "+f"(c[0]), "+f"(c[1]), "+f"(c[2]), "+f"(c[3])
        : "r"(a[0]), "r"(a[1]), "r"(a[2]), "r"(a[3]), "r"(b0), "r"(b1));
}

// --------------------------- CSR construction ------------------------------
__global__ void zero_deg_kernel() {
    int i = blockIdx.x * blockDim.x + threadIdx.x;
    if (i < NPn) { g_degW[i] = 0; g_degC[i] = 0; }
    if (i < NAn) { g_degA[i] = 0; }
}

__global__ void hist_all_kernel(const int* __restrict__ wdst,
                                const int* __restrict__ cdst,
                                const int* __restrict__ rdst) {
    const int T = EWn + ECn + ERn;
    for (int i = blockIdx.x * blockDim.x + threadIdx.x; i < T;
         i += gridDim.x * blockDim.x) {
        if (i < EWn)              atomicAdd(&g_degW[wdst[i]], 1);
        else if (i < EWn + ECn)   atomicAdd(&g_degC[cdst[i - EWn]], 1);
        else                      atomicAdd(&g_degA[rdst[i - EWn - ECn]], 1);
    }
}

__global__ void __launch_bounds__(1024) exscan3_kernel() {
    const int* deg; int* off; int* cur; int n;
    if (blockIdx.x == 0)      { deg = g_degW; off = g_offW; cur = g_curW; n = NPn; }
    else if (blockIdx.x == 1) { deg = g_degC; off = g_offC; cur = g_curC; n = NPn; }
    else                      { deg = g_degA; off = g_offA; cur = g_curA; n = NAn; }

    __shared__ int s[1024];
    const int tid = threadIdx.x;
    const int chunk = (n + 1023) / 1024;
    int lo = tid * chunk;
    int hi = lo + chunk; if (hi > n) hi = n; if (lo > n) lo = n;

    int sum = 0;
    for (int i = lo; i < hi; i++) sum += deg[i];
    s[tid] = sum;
    __syncthreads();

    #pragma unroll
    for (int d = 1; d < 1024; d <<= 1) {
        int v = (tid >= d) ? s[tid - d] : 0;
        __syncthreads();
        s[tid] += v;
        __syncthreads();
    }
    int run = s[tid] - sum;
    for (int i = lo; i < hi; i++) {
        off[i] = run;
        cur[i] = run;
        run += deg[i];
    }
    if (tid == 1023) off[n] = s[1023];
}

__global__ void fill_all_kernel(const int* __restrict__ wsrc, const int* __restrict__ wdst,
                                const int* __restrict__ csrc, const int* __restrict__ cdst,
                                const int* __restrict__ rsrc, const int* __restrict__ rdst) {
    const int T = EWn + ECn + ERn;
    for (int i = blockIdx.x * blockDim.x + threadIdx.x; i < T;
         i += gridDim.x * blockDim.x) {
        if (i < EWn) {
            int d = wdst[i];
            int p = atomicAdd(&g_curW[d], 1);
            g_srcW[p] = wsrc[i];
        } else if (i < EWn + ECn) {
            int j = i - EWn;
            int d = cdst[j];
            int p = atomicAdd(&g_curC[d], 1);
            g_srcC[p] = csrc[j];
        } else {
            int j = i - EWn - ECn;
            int d = rdst[j];
            int p = atomicAdd(&g_curA[d], 1);
            g_srcA[p] = rsrc[j];
        }
    }
}

// --------------------------- derived weights --------------------------------
__global__ void prep_weights_kernel(const float* __restrict__ Wr1,
                                    const float* __restrict__ bl1,
                                    const float* __restrict__ Wr2,
                                    const float* __restrict__ bl2) {
    int i = blockIdx.x * blockDim.x + threadIdx.x;
    if (i < DH * DIN)  g_Wc1[i] = 0.5f * (Wr1[i] + Wr1[DH * DIN + i]);
    if (i < DH)        g_bc1[i] = 0.5f * (bl1[i] + bl1[DH + i]);
    if (i < DOUT * DH) g_Wc2[i] = 0.5f * (Wr2[i] + Wr2[DOUT * DH + i]);
    if (i < DOUT)      g_bc2[i] = 0.5f * (bl2[i] + bl2[DOUT + i]);
}

// ---------------------- mma.sync split-bf16 GEMM ----------------------------
// C[M,BN] = act( (alpha*A[M,128]) @ W[BN,128]^T + bias + agg )
// alpha folded into W conversion. 3-term split: Ahi*Whi + Alo*Whi + Ahi*Wlo.
template <int BN>
__global__ void __launch_bounds__(256, 1)
tc_gemm(const float* __restrict__ A, const float* __restrict__ W,
        float* __restrict__ C, int M, float alpha,
        const float* __restrict__ bias, const float* __restrict__ agg,
        int do_relu) {
    constexpr int LDS = 136;        // bf16 elems per smem row (pad 8: conflict-free)
    constexpr int WN  = BN / 2;     // per-warp n extent
    constexpr int NT  = WN / 8;     // n tiles (m16n8) per warp

    extern __shared__ __align__(16) __nv_bfloat16 sm[];
    __nv_bfloat16* sAhi = sm;
    __nv_bfloat16* sAlo = sAhi + 128 * LDS;
    __nv_bfloat16* sWhi = sAlo + 128 * LDS;
    __nv_bfloat16* sWlo = sWhi + BN * LDS;

    const int tid  = threadIdx.x;
    const int lane = tid & 31;
    const int wid  = tid >> 5;
    const int m0   = blockIdx.x * 128;

    // ---- load + split-convert tiles into padded row-major SMEM ----
    const int cg = (tid & 15) * 8;  // 8 cols per thread
    for (int r = tid >> 4; r < 128; r += 16) {
        const int gm = m0 + r;
        float4 v0 = make_float4(0.f, 0.f, 0.f, 0.f);
        float4 v1 = v0;
        if (gm < M) {
            const float4* p = (const float4*)(A + (size_t)gm * 128 + cg);
            v0 = p[0];
            v1 = p[1];
        }
        float f[8] = {v0.x, v0.y, v0.z, v0.w, v1.x, v1.y, v1.z, v1.w};
        __nv_bfloat16 hi[8], lo[8];
        #pragma unroll
        for (int i = 0; i < 8; i++) {
            hi[i] = __float2bfloat16(f[i]);
            lo[i] = __float2bfloat16(f[i] - __bfloat162float(hi[i]));
        }
        *(uint4*)(sAhi + r * LDS + cg) = *(uint4*)hi;
        *(uint4*)(sAlo + r * LDS + cg) = *(uint4*)lo;
    }
    for (int r = tid >> 4; r < BN; r += 16) {
        const float4* p = (const float4*)(W + (size_t)r * 128 + cg);
        float4 v0 = p[0];
        float4 v1 = p[1];
        float f[8] = {v0.x, v0.y, v0.z, v0.w, v1.x, v1.y, v1.z, v1.w};
        __nv_bfloat16 hi[8], lo[8];
        #pragma unroll
        for (int i = 0; i < 8; i++) {
            const float s = alpha * f[i];
            hi[i] = __float2bfloat16(s);
            lo[i] = __float2bfloat16(s - __bfloat162float(hi[i]));
        }
        *(uint4*)(sWhi + r * LDS + cg) = *(uint4*)hi;
        *(uint4*)(sWlo + r * LDS + cg) = *(uint4*)lo;
    }
    __syncthreads();

    // ---- warp-tiled mma mainloop ----
    const int wm = (wid >> 1) * 32;
    const int wn = (wid & 1) * WN;

    float acc[2][NT][4];
    #pragma unroll
    for (int mt = 0; mt < 2; mt++)
        #pragma unroll
        for (int nt = 0; nt < NT; nt++)
            #pragma unroll
            for (int j = 0; j < 4; j++) acc[mt][nt][j] = 0.f;

    const uint32_t aAhi = smem_u32(sAhi);
    const uint32_t aAlo = smem_u32(sAlo);
    const uint32_t aWhi = smem_u32(sWhi);
    const uint32_t aWlo = smem_u32(sWlo);

    // ldmatrix lane addressing
    const int arow  = lane & 15;
    const int acol8 = (lane >> 4) * 8;
    const int brow  = (lane & 7) + ((lane >> 4) << 3);
    const int bcol8 = ((lane >> 3) & 1) * 8;

    #pragma unroll
    for (int k = 0; k < 8; k++) {
        const int kc = k * 16;
        uint32_t ahi[2][4], alo[2][4];
        #pragma unroll
        for (int mt = 0; mt < 2; mt++) {
            const uint32_t off =
                (uint32_t)((wm + mt * 16 + arow) * LDS + kc + acol8) * 2;
            ldmx4(ahi[mt], aAhi + off);
            ldmx4(alo[mt], aAlo + off);
        }
        #pragma unroll
        for (int np = 0; np < NT / 2; np++) {
            const uint32_t boff =
                (uint32_t)((wn + np * 16 + brow) * LDS + kc + bcol8) * 2;
            uint32_t bhi[4], blo[4];
            ldmx4(bhi, aWhi + boff);
            ldmx4(blo, aWlo + boff);
            #pragma unroll
            for (int mt = 0; mt < 2; mt++) {
                #pragma unroll
                for (int h = 0; h < 2; h++) {
                    float* c = acc[mt][np * 2 + h];
                    mma16816(c, ahi[mt], bhi[2 * h], bhi[2 * h + 1]);
                    mma16816(c, alo[mt], bhi[2 * h], bhi[2 * h + 1]);
                    mma16816(c, ahi[mt], blo[2 * h], blo[2 * h + 1]);
                }
            }
        }
    }

    // ---- epilogue: fused bias + agg + relu, direct gmem store ----
    #pragma unroll
    for (int mt = 0; mt < 2; mt++) {
        const int r0 = m0 + wm + mt * 16 + (lane >> 2);
        #pragma unroll
        for (int nt = 0; nt < NT; nt++) {
            const int col = wn + nt * 8 + (lane & 3) * 2;
            const float* c = acc[mt][nt];
            #pragma unroll
            for (int h = 0; h < 2; h++) {
                const int gm = r0 + h * 8;
                if (gm < M) {
                    float vx = c[2 * h], vy = c[2 * h + 1];
                    if (bias) { vx += bias[col]; vy += bias[col + 1]; }
                    if (agg) {
                        float2 g = *(const float2*)(agg + (size_t)gm * BN + col);
                        vx += g.x; vy += g.y;
                    }
                    if (do_relu) { vx = fmaxf(vx, 0.f); vy = fmaxf(vy, 0.f); }
                    *(float2*)(C + (size_t)gm * BN + col) = make_float2(vx, vy);
                }
            }
        }
    }
}

// ------------------------------ gather --------------------------------------
template <int VEC>
__global__ void gather_kernel(const int* __restrict__ off1, const int* __restrict__ src1,
                              const float* __restrict__ y1,
                              const int* __restrict__ off2, const int* __restrict__ src2,
                              const float* __restrict__ y2,
                              float* __restrict__ out, int n) {
    const int wid  = (blockIdx.x * blockDim.x + threadIdx.x) >> 5;
    const int lane = threadIdx.x & 31;
    if (wid >= n) return;
    constexpr int D = 32 * VEC;

    float res[VEC];
    #pragma unroll
    for (int v = 0; v < VEC; v++) res[v] = 0.f;

    const int* offs[2] = {off1, off2};
    const int* srcs[2] = {src1, src2};
    const float* ys[2] = {y1, y2};

    #pragma unroll
    for (int rel = 0; rel < 2; rel++) {
        if (!offs[rel]) break;
        const int b = offs[rel][wid];
        const int e = offs[rel][wid + 1];
        float acc[VEC];
        #pragma unroll
        for (int v = 0; v < VEC; v++) acc[v] = 0.f;

        int i = b;
        for (; i + 1 < e; i += 2) {
            const int s0 = __ldg(&srcs[rel][i]);
            const int s1 = __ldg(&srcs[rel][i + 1]);
            const float* r0 = ys[rel] + (size_t)s0 * D + lane * VEC;
            const float* r1 = ys[rel] + (size_t)s1 * D + lane * VEC;
            if (VEC == 4) {
                float4 t0 = *(const float4*)r0;
                float4 t1 = *(const float4*)r1;
                acc[0] += t0.x + t1.x; acc[1] += t0.y + t1.y;
                acc[2] += t0.z + t1.z; acc[3] += t0.w + t1.w;
            } else {
                float2 t0 = *(const float2*)r0;
                float2 t1 = *(const float2*)r1;
                acc[0] += t0.x + t1.x; acc[1] += t0.y + t1.y;
            }
        }
        if (i < e) {
            const int s0 = __ldg(&srcs[rel][i]);
            const float* r0 = ys[rel] + (size_t)s0 * D + lane * VEC;
            if (VEC == 4) {
                float4 t0 = *(const float4*)r0;
                acc[0] += t0.x; acc[1] += t0.y; acc[2] += t0.z; acc[3] += t0.w;
            } else {
                float2 t0 = *(const float2*)r0;
                acc[0] += t0.x; acc[1] += t0.y;
            }
        }
        const int deg = e - b;
        const float inv = deg > 0 ? 1.f / (float)deg : 0.f;
        #pragma unroll
        for (int v = 0; v < VEC; v++) res[v] += acc[v] * inv;
    }

    float* o = out + (size_t)wid * D + lane * VEC;
    if (VEC == 4) *(float4*)o = make_float4(res[0], res[1], res[2], res[3]);
    else          *(float2*)o = make_float2(res[0], res[1]);
}

// ------------------------------- launch -------------------------------------
extern "C" void kernel_launch(void* const* d_in, const int* in_sizes, int n_in,
                              void* d_out, int out_size) {
    const float* xp  = (const float*)d_in[0];
    const float* xa  = (const float*)d_in[1];
    const float* Wl1 = (const float*)d_in[2];
    const float* bl1 = (const float*)d_in[3];
    const float* Wr1 = (const float*)d_in[4];
    const float* Wl2 = (const float*)d_in[5];
    const float* bl2 = (const float*)d_in[6];
    const float* Wr2 = (const float*)d_in[7];
    const int* wsrc = (const int*)d_in[8];
    const int* wdst = (const int*)d_in[9];
    const int* csrc = (const int*)d_in[10];
    const int* cdst = (const int*)d_in[11];
    const int* rsrc = (const int*)d_in[12];
    const int* rdst = (const int*)d_in[13];
    float* out = (float*)d_out;

    float *p_ya, *p_yp, *p_yr, *p_aggP, *p_aggA, *p_hp1, *p_ha1, *p_za, *p_zp,
          *p_aggP2, *p_Wc1, *p_bc1, *p_Wc2, *p_bc2;
    int *p_offW, *p_offC, *p_offA, *p_srcW, *p_srcC, *p_srcA;
    cudaGetSymbolAddress((void**)&p_ya, g_ya);
    cudaGetSymbolAddress((void**)&p_yp, g_yp);
    cudaGetSymbolAddress((void**)&p_yr, g_yr);
    cudaGetSymbolAddress((void**)&p_aggP, g_aggP);
    cudaGetSymbolAddress((void**)&p_aggA, g_aggA);
    cudaGetSymbolAddress((void**)&p_hp1, g_hp1);
    cudaGetSymbolAddress((void**)&p_ha1, g_ha1);
    cudaGetSymbolAddress((void**)&p_za, g_za);
    cudaGetSymbolAddress((void**)&p_zp, g_zp);
    cudaGetSymbolAddress((void**)&p_aggP2, g_aggP2);
    cudaGetSymbolAddress((void**)&p_Wc1, g_Wc1);
    cudaGetSymbolAddress((void**)&p_bc1, g_bc1);
    cudaGetSymbolAddress((void**)&p_Wc2, g_Wc2);
    cudaGetSymbolAddress((void**)&p_bc2, g_bc2);
    cudaGetSymbolAddress((void**)&p_offW, g_offW);
    cudaGetSymbolAddress((void**)&p_offC, g_offC);
    cudaGetSymbolAddress((void**)&p_offA, g_offA);
    cudaGetSymbolAddress((void**)&p_srcW, g_srcW);
    cudaGetSymbolAddress((void**)&p_srcC, g_srcC);
    cudaGetSymbolAddress((void**)&p_srcA, g_srcA);

    // dynamic smem: (2*128 + 2*BN) rows * 136 bf16 * 2B
    constexpr int SMEM128 = (2 * 128 + 2 * 128) * 136 * 2;  // 139264
    constexpr int SMEM64  = (2 * 128 + 2 * 64) * 136 * 2;   // 104448
    cudaFuncSetAttribute(tc_gemm<128>, cudaFuncAttributeMaxDynamicSharedMemorySize, SMEM128);
    cudaFuncSetAttribute(tc_gemm<64>,  cudaFuncAttributeMaxDynamicSharedMemorySize, SMEM64);

    // ---- CSR build (shared by both layers) ----
    zero_deg_kernel<<<(NPn + 255) / 256, 256>>>();
    hist_all_kernel<<<1024, 256>>>(wdst, cdst, rdst);
    exscan3_kernel<<<3, 1024>>>();
    fill_all_kernel<<<1024, 256>>>(wsrc, wdst, csrc, cdst, rsrc, rdst);

    prep_weights_kernel<<<(DH * DIN + 255) / 256, 256>>>(Wr1, bl1, Wr2, bl2);

    const int gNP = (NPn + 127) / 128;   // 391
    const int gNA = (NAn + 127) / 128;   // 157
    const int gwP = (NPn * 32 + 255) / 256;
    const int gwA = (NAn * 32 + 255) / 256;

    // ---- Layer 1 ----
    tc_gemm<128><<<gNA, 256, SMEM128>>>(xa, Wl1 + 0 * DH * DIN, p_ya, NAn, 0.5f, nullptr, nullptr, 0);
    tc_gemm<128><<<gNP, 256, SMEM128>>>(xp, Wl1 + 1 * DH * DIN, p_yp, NPn, 0.5f, nullptr, nullptr, 0);
    tc_gemm<128><<<gNP, 256, SMEM128>>>(xp, Wl1 + 2 * DH * DIN, p_yr, NPn, 1.0f, nullptr, nullptr, 0);

    gather_kernel<4><<<gwP, 256>>>(p_offW, p_srcW, p_ya, p_offC, p_srcC, p_yp, p_aggP, NPn);
    gather_kernel<4><<<gwA, 256>>>(p_offA, p_srcA, p_yr, nullptr, nullptr, nullptr, p_aggA, NAn);

    tc_gemm<128><<<gNP, 256, SMEM128>>>(xp, p_Wc1, p_hp1, NPn, 1.0f, p_bc1, p_aggP, 1);
    tc_gemm<128><<<gNA, 256, SMEM128>>>(xa, Wr1 + 2 * DH * DIN, p_ha1, NAn, 1.0f, bl1 + 2 * DH, p_aggA, 1);

    // ---- Layer 2 (papers only; author output is dead) ----
    tc_gemm<64><<<gNA, 256, SMEM64>>>(p_ha1, Wl2 + 0 * DOUT * DH, p_za, NAn, 0.5f, nullptr, nullptr, 0);
    tc_gemm<64><<<gNP, 256, SMEM64>>>(p_hp1, Wl2 + 1 * DOUT * DH, p_zp, NPn, 0.5f, nullptr, nullptr, 0);

    gather_kernel<2><<<gwP, 256>>>(p_offW, p_srcW, p_za, p_offC, p_srcC, p_zp, p_aggP2, NPn);

    tc_gemm<64><<<gNP, 256, SMEM64>>>(p_hp1, p_Wc2, out, NPn, 1.0f, p_bc2, p_aggP2, 0);
}

// round 6
// speedup vs baseline: 1.8030x; 1.0296x over previous
#include <cuda_runtime.h>
#include <cuda_bf16.h>
#include <cuda_fp16.h>
#include <cstdint>

// ---------------------------------------------------------------------------
// RSAGE_Hetero round 4:
//  - mma.sync bf16 split GEMMs (unchanged math from round 3, passing)
//  - fp16 storage for gather-only intermediates (halves gather L2 traffic)
//  - merged launches: 3 L1-pre GEMMs -> 1, L1-post pair -> 1, L2-pre pair -> 1,
//    both L1 gathers -> 1, zero+prep -> 1   (17 -> 10 launches)
// ---------------------------------------------------------------------------

constexpr int NPn  = 50000;
constexpr int NAn  = 20000;
constexpr int DIN  = 128;
constexpr int DH   = 128;
constexpr int DOUT = 64;
constexpr int EWn  = 250000;
constexpr int ECn  = 500000;
constexpr int ERn  = 250000;

// ------------------------------ scratch ------------------------------------
__device__ __half g_yah[NAn * DH];     // 0.5 * xa @ Wl1[0]^T
__device__ __half g_yph[NPn * DH];     // 0.5 * xp @ Wl1[1]^T
__device__ __half g_yrh[NPn * DH];     //       xp @ Wl1[2]^T
__device__ __half g_zah[NAn * DOUT];   // 0.5 * ha1 @ Wl2[0]^T
__device__ __half g_zph[NPn * DOUT];   // 0.5 * hp1 @ Wl2[1]^T

__device__ float g_aggP[NPn * DH];
__device__ float g_aggA[NAn * DH];
__device__ float g_hp1[NPn * DH];
__device__ float g_ha1[NAn * DH];
__device__ float g_aggP2[NPn * DOUT];

__device__ int g_degW[NPn], g_degC[NPn], g_degA[NAn];
__device__ int g_offW[NPn + 1], g_offC[NPn + 1], g_offA[NAn + 1];
__device__ int g_curW[NPn], g_curC[NPn], g_curA[NAn];
__device__ int g_srcW[EWn], g_srcC[ECn], g_srcA[ERn];

__device__ float g_Wc1[DH * DIN];
__device__ float g_bc1[DH];
__device__ float g_Wc2[DOUT * DH];
__device__ float g_bc2[DOUT];

// --------------------------- PTX helpers -----------------------------------
__device__ __forceinline__ uint32_t smem_u32(const void* p) {
    uint32_t a;
    asm("{ .reg .u64 t; cvta.to.shared.u64 t, %1; cvt.u32.u64 %0, t; }"
        : "=r"(a) : "l"(p));
    return a;
}

__device__ __forceinline__ void ldmx4(uint32_t* r, uint32_t addr) {
    asm volatile(
        "ldmatrix.sync.aligned.m8n8.x4.shared.b16 {%0,%1,%2,%3}, [%4];"
        : "=r"(r[0]), "=r"(r[1]), "=r"(r[2]), "=r"(r[3]) : "r"(addr));
}

__device__ __forceinline__ void mma16816(float* c, const uint32_t* a,
                                         uint32_t b0, uint32_t b1) {
    asm volatile(
        "mma.sync.aligned.m16n8k16.row.col.f32.bf16.bf16.f32 "
        "{%0,%1,%2,%3}, {%4,%5,%6,%7}, {%8,%9}, {%0,%1,%2,%3};"
        : "+f"(c[0]), "+f"(c[1]), "+f"(c[2]), "+f"(c[3])
        : "r"(a[0]), "r"(a[1]), "r"(a[2]), "r"(a[3]), "r"(b0), "r"(b1));
}

// --------------------------- CSR construction ------------------------------
__global__ void zero_prep_kernel(const float* __restrict__ Wr1,
                                 const float* __restrict__ bl1,
                                 const float* __restrict__ Wr2,
                                 const float* __restrict__ bl2) {
    int i = blockIdx.x * blockDim.x + threadIdx.x;
    if (i < NPn) { g_degW[i] = 0; g_degC[i] = 0; }
    if (i < NAn) { g_degA[i] = 0; }
    if (i < DH * DIN)  g_Wc1[i] = 0.5f * (Wr1[i] + Wr1[DH * DIN + i]);
    if (i < DH)        g_bc1[i] = 0.5f * (bl1[i] + bl1[DH + i]);
    if (i < DOUT * DH) g_Wc2[i] = 0.5f * (Wr2[i] + Wr2[DOUT * DH + i]);
    if (i < DOUT)      g_bc2[i] = 0.5f * (bl2[i] + bl2[DOUT + i]);
}

__global__ void hist_all_kernel(const int* __restrict__ wdst,
                                const int* __restrict__ cdst,
                                const int* __restrict__ rdst) {
    const int T = EWn + ECn + ERn;
    for (int i = blockIdx.x * blockDim.x + threadIdx.x; i < T;
         i += gridDim.x * blockDim.x) {
        if (i < EWn)              atomicAdd(&g_degW[wdst[i]], 1);
        else if (i < EWn + ECn)   atomicAdd(&g_degC[cdst[i - EWn]], 1);
        else                      atomicAdd(&g_degA[rdst[i - EWn - ECn]], 1);
    }
}

__global__ void __launch_bounds__(1024) exscan3_kernel() {
    const int* deg; int* off; int* cur; int n;
    if (blockIdx.x == 0)      { deg = g_degW; off = g_offW; cur = g_curW; n = NPn; }
    else if (blockIdx.x == 1) { deg = g_degC; off = g_offC; cur = g_curC; n = NPn; }
    else                      { deg = g_degA; off = g_offA; cur = g_curA; n = NAn; }

    __shared__ int s[1024];
    const int tid = threadIdx.x;
    const int chunk = (n + 1023) / 1024;
    int lo = tid * chunk;
    int hi = lo + chunk; if (hi > n) hi = n; if (lo > n) lo = n;

    int sum = 0;
    for (int i = lo; i < hi; i++) sum += deg[i];
    s[tid] = sum;
    __syncthreads();

    #pragma unroll
    for (int d = 1; d < 1024; d <<= 1) {
        int v = (tid >= d) ? s[tid - d] : 0;
        __syncthreads();
        s[tid] += v;
        __syncthreads();
    }
    int run = s[tid] - sum;
    for (int i = lo; i < hi; i++) {
        off[i] = run;
        cur[i] = run;
        run += deg[i];
    }
    if (tid == 1023) off[n] = s[1023];
}

__global__ void fill_all_kernel(const int* __restrict__ wsrc, const int* __restrict__ wdst,
                                const int* __restrict__ csrc, const int* __restrict__ cdst,
                                const int* __restrict__ rsrc, const int* __restrict__ rdst) {
    const int T = EWn + ECn + ERn;
    for (int i = blockIdx.x * blockDim.x + threadIdx.x; i < T;
         i += gridDim.x * blockDim.x) {
        if (i < EWn) {
            int d = wdst[i];
            int p = atomicAdd(&g_curW[d], 1);
            g_srcW[p] = wsrc[i];
        } else if (i < EWn + ECn) {
            int j = i - EWn;
            int d = cdst[j];
            int p = atomicAdd(&g_curC[d], 1);
            g_srcC[p] = csrc[j];
        } else {
            int j = i - EWn - ECn;
            int d = rdst[j];
            int p = atomicAdd(&g_curA[d], 1);
            g_srcA[p] = rsrc[j];
        }
    }
}

// ---------------------- mma.sync split-bf16 GEMM ----------------------------
struct GTask {
    const float* A;
    const float* W;
    void* C;
    const float* bias;
    const float* agg;
    int M;
    int ctaEnd;
    float alpha;
    int relu;
};

// C[M,BN] = act( (alpha*A[M,128]) @ W[BN,128]^T + bias + agg )
// 3-term split: Ahi*Whi + Alo*Whi + Ahi*Wlo (fp32 accum).
template <int BN, typename OutT>
__global__ void __launch_bounds__(256, 1)
tc_gemm_multi(GTask t0, GTask t1, GTask t2) {
    constexpr int LDS = 136;        // bf16 elems per smem row (pad 8)
    constexpr int WN  = BN / 2;     // per-warp n extent
    constexpr int NT  = WN / 8;     // m16n8 tiles per warp

    GTask t;
    int base;
    if ((int)blockIdx.x < t0.ctaEnd)      { t = t0; base = 0; }
    else if ((int)blockIdx.x < t1.ctaEnd) { t = t1; base = t0.ctaEnd; }
    else                                  { t = t2; base = t1.ctaEnd; }

    const float* __restrict__ A    = t.A;
    const float* __restrict__ W    = t.W;
    const float* __restrict__ bias = t.bias;
    const float* __restrict__ agg  = t.agg;
    OutT* __restrict__ C = (OutT*)t.C;
    const int M = t.M;
    const float alpha = t.alpha;
    const int do_relu = t.relu;

    extern __shared__ __align__(16) __nv_bfloat16 sm[];
    __nv_bfloat16* sAhi = sm;
    __nv_bfloat16* sAlo = sAhi + 128 * LDS;
    __nv_bfloat16* sWhi = sAlo + 128 * LDS;
    __nv_bfloat16* sWlo = sWhi + BN * LDS;

    const int tid  = threadIdx.x;
    const int lane = tid & 31;
    const int wid  = tid >> 5;
    const int m0   = ((int)blockIdx.x - base) * 128;

    // ---- load + split-convert tiles ----
    const int cg = (tid & 15) * 8;
    for (int r = tid >> 4; r < 128; r += 16) {
        const int gm = m0 + r;
        float4 v0 = make_float4(0.f, 0.f, 0.f, 0.f);
        float4 v1 = v0;
        if (gm < M) {
            const float4* p = (const float4*)(A + (size_t)gm * 128 + cg);
            v0 = p[0];
            v1 = p[1];
        }
        float f[8] = {v0.x, v0.y, v0.z, v0.w, v1.x, v1.y, v1.z, v1.w};
        __nv_bfloat16 hi[8], lo[8];
        #pragma unroll
        for (int i = 0; i < 8; i++) {
            hi[i] = __float2bfloat16(f[i]);
            lo[i] = __float2bfloat16(f[i] - __bfloat162float(hi[i]));
        }
        *(uint4*)(sAhi + r * LDS + cg) = *(uint4*)hi;
        *(uint4*)(sAlo + r * LDS + cg) = *(uint4*)lo;
    }
    for (int r = tid >> 4; r < BN; r += 16) {
        const float4* p = (const float4*)(W + (size_t)r * 128 + cg);
        float4 v0 = p[0];
        float4 v1 = p[1];
        float f[8] = {v0.x, v0.y, v0.z, v0.w, v1.x, v1.y, v1.z, v1.w};
        __nv_bfloat16 hi[8], lo[8];
        #pragma unroll
        for (int i = 0; i < 8; i++) {
            const float s = alpha * f[i];
            hi[i] = __float2bfloat16(s);
            lo[i] = __float2bfloat16(s - __bfloat162float(hi[i]));
        }
        *(uint4*)(sWhi + r * LDS + cg) = *(uint4*)hi;
        *(uint4*)(sWlo + r * LDS + cg) = *(uint4*)lo;
    }
    __syncthreads();

    // ---- warp-tiled mma mainloop ----
    const int wm = (wid >> 1) * 32;
    const int wn = (wid & 1) * WN;

    float acc[2][NT][4];
    #pragma unroll
    for (int mt = 0; mt < 2; mt++)
        #pragma unroll
        for (int nt = 0; nt < NT; nt++)
            #pragma unroll
            for (int j = 0; j < 4; j++) acc[mt][nt][j] = 0.f;

    const uint32_t aAhi = smem_u32(sAhi);
    const uint32_t aAlo = smem_u32(sAlo);
    const uint32_t aWhi = smem_u32(sWhi);
    const uint32_t aWlo = smem_u32(sWlo);

    const int arow  = lane & 15;
    const int acol8 = (lane >> 4) * 8;
    const int brow  = (lane & 7) + ((lane >> 4) << 3);
    const int bcol8 = ((lane >> 3) & 1) * 8;

    #pragma unroll
    for (int k = 0; k < 8; k++) {
        const int kc = k * 16;
        uint32_t ahi[2][4], alo[2][4];
        #pragma unroll
        for (int mt = 0; mt < 2; mt++) {
            const uint32_t off =
                (uint32_t)((wm + mt * 16 + arow) * LDS + kc + acol8) * 2;
            ldmx4(ahi[mt], aAhi + off);
            ldmx4(alo[mt], aAlo + off);
        }
        #pragma unroll
        for (int np = 0; np < NT / 2; np++) {
            const uint32_t boff =
                (uint32_t)((wn + np * 16 + brow) * LDS + kc + bcol8) * 2;
            uint32_t bhi[4], blo[4];
            ldmx4(bhi, aWhi + boff);
            ldmx4(blo, aWlo + boff);
            #pragma unroll
            for (int mt = 0; mt < 2; mt++) {
                #pragma unroll
                for (int h = 0; h < 2; h++) {
                    float* c = acc[mt][np * 2 + h];
                    mma16816(c, ahi[mt], bhi[2 * h], bhi[2 * h + 1]);
                    mma16816(c, alo[mt], bhi[2 * h], bhi[2 * h + 1]);
                    mma16816(c, ahi[mt], blo[2 * h], blo[2 * h + 1]);
                }
            }
        }
    }

    // ---- epilogue ----
    #pragma unroll
    for (int mt = 0; mt < 2; mt++) {
        const int r0 = m0 + wm + mt * 16 + (lane >> 2);
        #pragma unroll
        for (int nt = 0; nt < NT; nt++) {
            const int col = wn + nt * 8 + (lane & 3) * 2;
            const float* c = acc[mt][nt];
            #pragma unroll
            for (int h = 0; h < 2; h++) {
                const int gm = r0 + h * 8;
                if (gm < M) {
                    float vx = c[2 * h], vy = c[2 * h + 1];
                    if (bias) { vx += bias[col]; vy += bias[col + 1]; }
                    if (agg) {
                        float2 g = *(const float2*)(agg + (size_t)gm * BN + col);
                        vx += g.x; vy += g.y;
                    }
                    if (do_relu) { vx = fmaxf(vx, 0.f); vy = fmaxf(vy, 0.f); }
                    if (sizeof(OutT) == 2) {
                        *(__half2*)((__half*)C + (size_t)gm * BN + col) =
                            __floats2half2_rn(vx, vy);
                    } else {
                        *(float2*)((float*)C + (size_t)gm * BN + col) =
                            make_float2(vx, vy);
                    }
                }
            }
        }
    }
}

// ------------------------------ gather --------------------------------------
// mean over up to 2 relations of fp16 rows; fp32 accumulate + fp32 output.
// HPL = halfs per lane (4 -> D=128, 2 -> D=64)
template <int HPL>
__device__ __forceinline__ void gather_node(
    int node, int lane,
    const int* __restrict__ off1, const int* __restrict__ src1,
    const __half* __restrict__ y1,
    const int* __restrict__ off2, const int* __restrict__ src2,
    const __half* __restrict__ y2,
    float* __restrict__ out) {
    constexpr int D = 32 * HPL;

    float res[HPL];
    #pragma unroll
    for (int v = 0; v < HPL; v++) res[v] = 0.f;

    const int* offs[2] = {off1, off2};
    const int* srcs[2] = {src1, src2};
    const __half* ys[2] = {y1, y2};

    #pragma unroll
    for (int rel = 0; rel < 2; rel++) {
        if (!offs[rel]) break;
        const int b = offs[rel][node];
        const int e = offs[rel][node + 1];
        float acc[HPL];
        #pragma unroll
        for (int v = 0; v < HPL; v++) acc[v] = 0.f;

        int i = b;
        for (; i + 1 < e; i += 2) {
            const int s0 = __ldg(&srcs[rel][i]);
            const int s1 = __ldg(&srcs[rel][i + 1]);
            const __half* r0 = ys[rel] + (size_t)s0 * D + lane * HPL;
            const __half* r1 = ys[rel] + (size_t)s1 * D + lane * HPL;
            if (HPL == 4) {
                uint2 u0 = *(const uint2*)r0;
                uint2 u1 = *(const uint2*)r1;
                float2 a0 = __half22float2(*(const __half2*)&u0.x);
                float2 a1 = __half22float2(*(const __half2*)&u0.y);
                float2 b0 = __half22float2(*(const __half2*)&u1.x);
                float2 b1 = __half22float2(*(const __half2*)&u1.y);
                acc[0] += a0.x + b0.x; acc[1] += a0.y + b0.y;
                acc[2] += a1.x + b1.x; acc[3] += a1.y + b1.y;
            } else {
                float2 a0 = __half22float2(*(const __half2*)r0);
                float2 b0 = __half22float2(*(const __half2*)r1);
                acc[0] += a0.x + b0.x; acc[1] += a0.y + b0.y;
            }
        }
        if (i < e) {
            const int s0 = __ldg(&srcs[rel][i]);
            const __half* r0 = ys[rel] + (size_t)s0 * D + lane * HPL;
            if (HPL == 4) {
                uint2 u0 = *(const uint2*)r0;
                float2 a0 = __half22float2(*(const __half2*)&u0.x);
                float2 a1 = __half22float2(*(const __half2*)&u0.y);
                acc[0] += a0.x; acc[1] += a0.y;
                acc[2] += a1.x; acc[3] += a1.y;
            } else {
                float2 a0 = __half22float2(*(const __half2*)r0);
                acc[0] += a0.x; acc[1] += a0.y;
            }
        }
        const int deg = e - b;
        const float inv = deg > 0 ? 1.f / (float)deg : 0.f;
        #pragma unroll
        for (int v = 0; v < HPL; v++) res[v] += acc[v] * inv;
    }

    float* o = out + (size_t)node * D + lane * HPL;
    if (HPL == 4) *(float4*)o = make_float4(res[0], res[1], res[2], res[3]);
    else          *(float2*)o = make_float2(res[0], res[1]);
}

// Layer-1 gathers fused: papers (writes + cites) then authors (rev).
__global__ void gather_l1_kernel() {
    const int gw   = (blockIdx.x * blockDim.x + threadIdx.x) >> 5;
    const int lane = threadIdx.x & 31;
    if (gw < NPn) {
        gather_node<4>(gw, lane, g_offW, g_srcW, g_yah,
                       g_offC, g_srcC, g_yph, g_aggP);
    } else if (gw < NPn + NAn) {
        gather_node<4>(gw - NPn, lane, g_offA, g_srcA, g_yrh,
                       nullptr, nullptr, nullptr, g_aggA);
    }
}

// Layer-2 gather: papers only (writes + cites), D=64.
__global__ void gather_l2_kernel() {
    const int gw   = (blockIdx.x * blockDim.x + threadIdx.x) >> 5;
    const int lane = threadIdx.x & 31;
    if (gw < NPn) {
        gather_node<2>(gw, lane, g_offW, g_srcW, g_zah,
                       g_offC, g_srcC, g_zph, g_aggP2);
    }
}

// ------------------------------- launch -------------------------------------
extern "C" void kernel_launch(void* const* d_in, const int* in_sizes, int n_in,
                              void* d_out, int out_size) {
    const float* xp  = (const float*)d_in[0];
    const float* xa  = (const float*)d_in[1];
    const float* Wl1 = (const float*)d_in[2];
    const float* bl1 = (const float*)d_in[3];
    const float* Wr1 = (const float*)d_in[4];
    const float* Wl2 = (const float*)d_in[5];
    const float* bl2 = (const float*)d_in[6];
    const float* Wr2 = (const float*)d_in[7];
    const int* wsrc = (const int*)d_in[8];
    const int* wdst = (const int*)d_in[9];
    const int* csrc = (const int*)d_in[10];
    const int* cdst = (const int*)d_in[11];
    const int* rsrc = (const int*)d_in[12];
    const int* rdst = (const int*)d_in[13];
    float* out = (float*)d_out;

    // resolve scratch symbol addresses
    __half *p_yah, *p_yph, *p_yrh, *p_zah, *p_zph;
    float *p_aggP, *p_aggA, *p_hp1, *p_ha1, *p_aggP2, *p_Wc1, *p_bc1, *p_Wc2, *p_bc2;
    cudaGetSymbolAddress((void**)&p_yah, g_yah);
    cudaGetSymbolAddress((void**)&p_yph, g_yph);
    cudaGetSymbolAddress((void**)&p_yrh, g_yrh);
    cudaGetSymbolAddress((void**)&p_zah, g_zah);
    cudaGetSymbolAddress((void**)&p_zph, g_zph);
    cudaGetSymbolAddress((void**)&p_aggP, g_aggP);
    cudaGetSymbolAddress((void**)&p_aggA, g_aggA);
    cudaGetSymbolAddress((void**)&p_hp1, g_hp1);
    cudaGetSymbolAddress((void**)&p_ha1, g_ha1);
    cudaGetSymbolAddress((void**)&p_aggP2, g_aggP2);
    cudaGetSymbolAddress((void**)&p_Wc1, g_Wc1);
    cudaGetSymbolAddress((void**)&p_bc1, g_bc1);
    cudaGetSymbolAddress((void**)&p_Wc2, g_Wc2);
    cudaGetSymbolAddress((void**)&p_bc2, g_bc2);

    constexpr int SMEM128 = (2 * 128 + 2 * 128) * 136 * 2;  // 139264
    constexpr int SMEM64  = (2 * 128 + 2 * 64) * 136 * 2;   // 104448
    cudaFuncSetAttribute((const void*)tc_gemm_multi<128, __half>,
                         cudaFuncAttributeMaxDynamicSharedMemorySize, SMEM128);
    cudaFuncSetAttribute((const void*)tc_gemm_multi<128, float>,
                         cudaFuncAttributeMaxDynamicSharedMemorySize, SMEM128);
    cudaFuncSetAttribute((const void*)tc_gemm_multi<64, __half>,
                         cudaFuncAttributeMaxDynamicSharedMemorySize, SMEM64);
    cudaFuncSetAttribute((const void*)tc_gemm_multi<64, float>,
                         cudaFuncAttributeMaxDynamicSharedMemorySize, SMEM64);

    const int gNP = (NPn + 127) / 128;   // 391
    const int gNA = (NAn + 127) / 128;   // 157

    // ---- CSR build + derived weights ----
    zero_prep_kernel<<<(NPn + 255) / 256, 256>>>(Wr1, bl1, Wr2, bl2);
    hist_all_kernel<<<1024, 256>>>(wdst, cdst, rdst);
    exscan3_kernel<<<3, 1024>>>();
    fill_all_kernel<<<1024, 256>>>(wsrc, wdst, csrc, cdst, rsrc, rdst);

    // ---- Layer 1 pre-GEMMs (ya | yp | yr), fp16 outputs ----
    {
        GTask ta = {xa, Wl1 + 0 * DH * DIN, p_yah, nullptr, nullptr,
                    NAn, gNA, 0.5f, 0};
        GTask tp = {xp, Wl1 + 1 * DH * DIN, p_yph, nullptr, nullptr,
                    NPn, gNA + gNP, 0.5f, 0};
        GTask tr = {xp, Wl1 + 2 * DH * DIN, p_yrh, nullptr, nullptr,
                    NPn, gNA + 2 * gNP, 1.0f, 0};
        tc_gemm_multi<128, __half><<<gNA + 2 * gNP, 256, SMEM128>>>(ta, tp, tr);
    }

    // ---- Layer 1 gathers (papers + authors fused) ----
    {
        const int warps = NPn + NAn;
        gather_l1_kernel<<<(warps * 32 + 255) / 256, 256>>>();
    }

    // ---- Layer 1 post-GEMMs (hp1 | ha1), fp32 outputs, relu ----
    {
        GTask th = {xp, p_Wc1, p_hp1, p_bc1, p_aggP, NPn, gNP, 1.0f, 1};
        GTask tA = {xa, Wr1 + 2 * DH * DIN, p_ha1, bl1 + 2 * DH, p_aggA,
                    NAn, gNP + gNA, 1.0f, 1};
        tc_gemm_multi<128, float><<<gNP + gNA, 256, SMEM128>>>(th, tA, tA);
    }

    // ---- Layer 2 pre-GEMMs (za | zp), fp16 outputs ----
    {
        GTask ta = {p_ha1, Wl2 + 0 * DOUT * DH, p_zah, nullptr, nullptr,
                    NAn, gNA, 0.5f, 0};
        GTask tp = {p_hp1, Wl2 + 1 * DOUT * DH, p_zph, nullptr, nullptr,
                    NPn, gNA + gNP, 0.5f, 0};
        tc_gemm_multi<64, __half><<<gNA + gNP, 256, SMEM64>>>(ta, tp, tp);
    }

    // ---- Layer 2 gather (papers) ----
    gather_l2_kernel<<<(NPn * 32 + 255) / 256, 256>>>();

    // ---- Final GEMM -> out ----
    {
        GTask tf = {p_hp1, p_Wc2, out, p_bc2, p_aggP2, NPn, gNP, 1.0f, 0};
        tc_gemm_multi<64, float><<<gNP, 256, SMEM64>>>(tf, tf, tf);
    }
}

// round 7
// speedup vs baseline: 2.6757x; 1.4840x over previous
#include <cuda_runtime.h>
#include <cuda_bf16.h>
#include <cuda_fp16.h>
#include <cstdint>

// ---------------------------------------------------------------------------
// RSAGE_Hetero round 6: critical-path restructuring.
//  - self-term GEMMs hoisted before gathers (relu fused into gather epilogue)
//  - hist CTAs overlapped inside L1 mega-GEMM launch
//  - unified 3-relation CSR with one global scan (3 fast kernels)
//  - hp1/ha1 produced as bf16 hi/lo pairs by the gather (no re-split downstream)
//  - final GEMM folded into L2 mega-launch; gather_l2 writes d_out
//  9 launches total.
// ---------------------------------------------------------------------------

constexpr int NPn  = 50000;
constexpr int NAn  = 20000;
constexpr int DIN  = 128;
constexpr int DH   = 128;
constexpr int DOUT = 64;
constexpr int EWn  = 250000;
constexpr int ECn  = 500000;
constexpr int ERn  = 250000;
constexpr int NT   = 2 * NPn + NAn;          // unified node slots (W|C|A)
constexpr int ET   = EWn + ECn + ERn;        // total edges
constexpr int NB   = (NT + 1023) / 1024;     // scan blocks (118)
constexpr int HISTC = 192;                   // hist CTAs inside L1 mega launch

// ------------------------------ scratch ------------------------------------
__device__ __half g_yah[NAn * DH];           // 0.5 * xa @ Wl1[0]^T
__device__ __half g_yph[NPn * DH];           // 0.5 * xp @ Wl1[1]^T
__device__ __half g_yrh[NPn * DH];           //       xp @ Wl1[2]^T
__device__ __half g_zah[NAn * DOUT];         // 0.5 * ha1 @ Wl2[0]^T
__device__ __half g_zph[NPn * DOUT];         // 0.5 * hp1 @ Wl2[1]^T
__device__ float  g_S1p[NPn * DH];           // xp @ Wc1^T + bc1
__device__ float  g_S1a[NAn * DH];           // xa @ Wr1[2]^T + bl1[2]
__device__ float  g_S2 [NPn * DOUT];         // hp1 @ Wc2^T + bc2
__device__ __nv_bfloat16 g_hp1h[NPn * DH], g_hp1l[NPn * DH];
__device__ __nv_bfloat16 g_ha1h[NAn * DH], g_ha1l[NAn * DH];

__device__ int g_deg[NT], g_off[NT + 1], g_cur[NT], g_src[ET];
__device__ int g_bsum[NB], g_bbase[NB];

__device__ float g_Wc1[DH * DIN];
__device__ float g_bc1[DH];
__device__ float g_Wc2[DOUT * DH];
__device__ float g_bc2[DOUT];

// --------------------------- PTX helpers -----------------------------------
__device__ __forceinline__ uint32_t smem_u32(const void* p) {
    uint32_t a;
    asm("{ .reg .u64 t; cvta.to.shared.u64 t, %1; cvt.u32.u64 %0, t; }"
        : "=r"(a) : "l"(p));
    return a;
}

__device__ __forceinline__ void ldmx4(uint32_t* r, uint32_t addr) {
    asm volatile(
        "ldmatrix.sync.aligned.m8n8.x4.shared.b16 {%0,%1,%2,%3}, [%4];"
        : "=r"(r[0]), "=r"(r[1]), "=r"(r[2]), "=r"(r[3]) : "r"(addr));
}

__device__ __forceinline__ void mma16816(float* c, const uint32_t* a,
                                         uint32_t b0, uint32_t b1) {
    asm volatile(
        "mma.sync.aligned.m16n8k16.row.col.f32.bf16.bf16.f32 "
        "{%0,%1,%2,%3}, {%4,%5,%6,%7}, {%8,%9}, {%0,%1,%2,%3};"
        : "+f"(c[0]), "+f"(c[1]), "+f"(c[2]), "+f"(c[3])
        : "r"(a[0]), "r"(a[1]), "r"(a[2]), "r"(a[3]), "r"(b0), "r"(b1));
}

// --------------------------- setup / CSR ------------------------------------
__global__ void zero_prep_kernel(const float* __restrict__ Wr1,
                                 const float* __restrict__ bl1,
                                 const float* __restrict__ Wr2,
                                 const float* __restrict__ bl2) {
    int i = blockIdx.x * blockDim.x + threadIdx.x;
    if (i < NT) g_deg[i] = 0;
    if (i < DH * DIN)  g_Wc1[i] = 0.5f * (Wr1[i] + Wr1[DH * DIN + i]);
    if (i < DH)        g_bc1[i] = 0.5f * (bl1[i] + bl1[DH + i]);
    if (i < DOUT * DH) g_Wc2[i] = 0.5f * (Wr2[i] + Wr2[DOUT * DH + i]);
    if (i < DOUT)      g_bc2[i] = 0.5f * (bl2[i] + bl2[DOUT + i]);
}

// unified scan: S1 blocksums -> S2 base scan -> S3 apply
__global__ void scan_bsum_kernel() {
    __shared__ int s[256];
    const int tid = threadIdx.x;
    const int i0 = blockIdx.x * 1024 + tid * 4;
    int sum = 0;
    #pragma unroll
    for (int k = 0; k < 4; k++)
        if (i0 + k < NT) sum += g_deg[i0 + k];
    s[tid] = sum;
    __syncthreads();
    #pragma unroll
    for (int d = 128; d > 0; d >>= 1) {
        if (tid < d) s[tid] += s[tid + d];
        __syncthreads();
    }
    if (tid == 0) g_bsum[blockIdx.x] = s[0];
}

__global__ void scan_base_kernel() {
    __shared__ int s[128];
    const int tid = threadIdx.x;
    int v = (tid < NB) ? g_bsum[tid] : 0;
    s[tid] = v;
    __syncthreads();
    #pragma unroll
    for (int d = 1; d < 128; d <<= 1) {
        int t = (tid >= d) ? s[tid - d] : 0;
        __syncthreads();
        s[tid] += t;
        __syncthreads();
    }
    if (tid < NB) g_bbase[tid] = s[tid] - v;   // exclusive
    if (tid == 127) g_off[NT] = s[127];        // total edges
}

__global__ void scan_apply_kernel() {
    __shared__ int s[256];
    const int tid = threadIdx.x;
    const int i0 = blockIdx.x * 1024 + tid * 4;
    int e[4];
    int sum = 0;
    #pragma unroll
    for (int k = 0; k < 4; k++) {
        e[k] = (i0 + k < NT) ? g_deg[i0 + k] : 0;
        sum += e[k];
    }
    s[tid] = sum;
    __syncthreads();
    #pragma unroll
    for (int d = 1; d < 256; d <<= 1) {
        int t = (tid >= d) ? s[tid - d] : 0;
        __syncthreads();
        s[tid] += t;
        __syncthreads();
    }
    int run = g_bbase[blockIdx.x] + s[tid] - sum;
    #pragma unroll
    for (int k = 0; k < 4; k++) {
        if (i0 + k < NT) {
            g_off[i0 + k] = run;
            g_cur[i0 + k] = run;
            run += e[k];
        }
    }
}

__global__ void fill_all_kernel(const int* __restrict__ wsrc, const int* __restrict__ wdst,
                                const int* __restrict__ csrc, const int* __restrict__ cdst,
                                const int* __restrict__ rsrc, const int* __restrict__ rdst) {
    for (int i = blockIdx.x * blockDim.x + threadIdx.x; i < ET;
         i += gridDim.x * blockDim.x) {
        int node, sv;
        if (i < EWn)            { node = wdst[i]; sv = wsrc[i]; }
        else if (i < EWn + ECn) { int j = i - EWn; node = NPn + cdst[j]; sv = csrc[j]; }
        else                    { int j = i - EWn - ECn; node = 2 * NPn + rdst[j]; sv = rsrc[j]; }
        int p = atomicAdd(&g_cur[node], 1);
        g_src[p] = sv;
    }
}

// ---------------------- mma.sync split-bf16 mega GEMM -----------------------
struct GTask {
    const void* A;        // fp32 rows, or bf16 hi rows if Alo != null
    const void* Alo;      // bf16 lo rows (null -> fp32 split on the fly)
    const float* W;       // fp32 [BN,128]
    void* C;
    const float* bias;    // nullable
    int M;
    int ctaEnd;           // absolute (includes hist offset)
    int outHalf;          // 1 -> __half output, 0 -> float
    float alpha;          // folded into W conversion
};

// C[M,BN] = (alpha-scaled) A[M,128] @ W[BN,128]^T + bias
// 3-term split: Ahi*Whi + Alo*Whi + Ahi*Wlo (fp32 accum).
// Blocks [0,histC) do the degree histogram instead (L1 launch only).
template <int BN>
__global__ void __launch_bounds__(256, 1)
tc_mega(GTask t0, GTask t1, GTask t2, GTask t3, GTask t4, int histC,
        const int* wsrc, const int* wdst, const int* csrc, const int* cdst,
        const int* rsrc, const int* rdst) {
    constexpr int LDS = 136;
    constexpr int WN  = BN / 2;
    constexpr int NT_ = WN / 8;

    const int bId = blockIdx.x;
    if (bId < histC) {
        // ---- histogram role (overlapped with GEMM waves) ----
        const int stride = histC * 256;
        for (int i = bId * 256 + threadIdx.x; i < ET; i += stride) {
            int node;
            if (i < EWn)            node = wdst[i];
            else if (i < EWn + ECn) node = NPn + cdst[i - EWn];
            else                    node = 2 * NPn + rdst[i - EWn - ECn];
            atomicAdd(&g_deg[node], 1);
        }
        return;
    }

    GTask t;
    int base;
    if (bId < t0.ctaEnd)      { t = t0; base = histC; }
    else if (bId < t1.ctaEnd) { t = t1; base = t0.ctaEnd; }
    else if (bId < t2.ctaEnd) { t = t2; base = t1.ctaEnd; }
    else if (bId < t3.ctaEnd) { t = t3; base = t2.ctaEnd; }
    else                      { t = t4; base = t3.ctaEnd; }

    const float* __restrict__ W    = t.W;
    const float* __restrict__ bias = t.bias;
    const int M = t.M;
    const float alpha = t.alpha;

    extern __shared__ __align__(16) __nv_bfloat16 sm[];
    __nv_bfloat16* sAhi = sm;
    __nv_bfloat16* sAlo = sAhi + 128 * LDS;
    __nv_bfloat16* sWhi = sAlo + 128 * LDS;
    __nv_bfloat16* sWlo = sWhi + BN * LDS;

    const int tid  = threadIdx.x;
    const int lane = tid & 31;
    const int wid  = tid >> 5;
    const int m0   = (bId - base) * 128;

    // ---- A tiles ----
    const int cg = (tid & 15) * 8;
    if (t.Alo) {
        const __nv_bfloat16* Ah = (const __nv_bfloat16*)t.A;
        const __nv_bfloat16* Al = (const __nv_bfloat16*)t.Alo;
        for (int r = tid >> 4; r < 128; r += 16) {
            const int gm = m0 + r;
            uint4 vh = make_uint4(0, 0, 0, 0), vl = vh;
            if (gm < M) {
                vh = *(const uint4*)(Ah + (size_t)gm * 128 + cg);
                vl = *(const uint4*)(Al + (size_t)gm * 128 + cg);
            }
            *(uint4*)(sAhi + r * LDS + cg) = vh;
            *(uint4*)(sAlo + r * LDS + cg) = vl;
        }
    } else {
        const float* A = (const float*)t.A;
        for (int r = tid >> 4; r < 128; r += 16) {
            const int gm = m0 + r;
            float4 v0 = make_float4(0.f, 0.f, 0.f, 0.f), v1 = v0;
            if (gm < M) {
                const float4* p = (const float4*)(A + (size_t)gm * 128 + cg);
                v0 = p[0];
                v1 = p[1];
            }
            float f[8] = {v0.x, v0.y, v0.z, v0.w, v1.x, v1.y, v1.z, v1.w};
            __nv_bfloat16 hi[8], lo[8];
            #pragma unroll
            for (int i = 0; i < 8; i++) {
                hi[i] = __float2bfloat16(f[i]);
                lo[i] = __float2bfloat16(f[i] - __bfloat162float(hi[i]));
            }
            *(uint4*)(sAhi + r * LDS + cg) = *(uint4*)hi;
            *(uint4*)(sAlo + r * LDS + cg) = *(uint4*)lo;
        }
    }
    // ---- W tiles (fp32 -> alpha-scaled split) ----
    for (int r = tid >> 4; r < BN; r += 16) {
        const float4* p = (const float4*)(W + (size_t)r * 128 + cg);
        float4 v0 = p[0];
        float4 v1 = p[1];
        float f[8] = {v0.x, v0.y, v0.z, v0.w, v1.x, v1.y, v1.z, v1.w};
        __nv_bfloat16 hi[8], lo[8];
        #pragma unroll
        for (int i = 0; i < 8; i++) {
            const float s = alpha * f[i];
            hi[i] = __float2bfloat16(s);
            lo[i] = __float2bfloat16(s - __bfloat162float(hi[i]));
        }
        *(uint4*)(sWhi + r * LDS + cg) = *(uint4*)hi;
        *(uint4*)(sWlo + r * LDS + cg) = *(uint4*)lo;
    }
    __syncthreads();

    // ---- warp-tiled mma mainloop (proven round-3 layout) ----
    const int wm = (wid >> 1) * 32;
    const int wn = (wid & 1) * WN;

    float acc[2][NT_][4];
    #pragma unroll
    for (int mt = 0; mt < 2; mt++)
        #pragma unroll
        for (int nt = 0; nt < NT_; nt++)
            #pragma unroll
            for (int j = 0; j < 4; j++) acc[mt][nt][j] = 0.f;

    const uint32_t aAhi = smem_u32(sAhi);
    const uint32_t aAlo = smem_u32(sAlo);
    const uint32_t aWhi = smem_u32(sWhi);
    const uint32_t aWlo = smem_u32(sWlo);

    const int arow  = lane & 15;
    const int acol8 = (lane >> 4) * 8;
    const int brow  = (lane & 7) + ((lane >> 4) << 3);
    const int bcol8 = ((lane >> 3) & 1) * 8;

    #pragma unroll
    for (int k = 0; k < 8; k++) {
        const int kc = k * 16;
        uint32_t ahi[2][4], alo[2][4];
        #pragma unroll
        for (int mt = 0; mt < 2; mt++) {
            const uint32_t off =
                (uint32_t)((wm + mt * 16 + arow) * LDS + kc + acol8) * 2;
            ldmx4(ahi[mt], aAhi + off);
            ldmx4(alo[mt], aAlo + off);
        }
        #pragma unroll
        for (int np = 0; np < NT_ / 2; np++) {
            const uint32_t boff =
                (uint32_t)((wn + np * 16 + brow) * LDS + kc + bcol8) * 2;
            uint32_t bhi[4], blo[4];
            ldmx4(bhi, aWhi + boff);
            ldmx4(blo, aWlo + boff);
            #pragma unroll
            for (int mt = 0; mt < 2; mt++) {
                #pragma unroll
                for (int h = 0; h < 2; h++) {
                    float* c = acc[mt][np * 2 + h];
                    mma16816(c, ahi[mt], bhi[2 * h], bhi[2 * h + 1]);
                    mma16816(c, alo[mt], bhi[2 * h], bhi[2 * h + 1]);
                    mma16816(c, ahi[mt], blo[2 * h], blo[2 * h + 1]);
                }
            }
        }
    }

    // ---- epilogue: optional bias, half/float output ----
    #pragma unroll
    for (int mt = 0; mt < 2; mt++) {
        const int r0 = m0 + wm + mt * 16 + (lane >> 2);
        #pragma unroll
        for (int nt = 0; nt < NT_; nt++) {
            const int col = wn + nt * 8 + (lane & 3) * 2;
            const float* c = acc[mt][nt];
            #pragma unroll
            for (int h = 0; h < 2; h++) {
                const int gm = r0 + h * 8;
                if (gm < M) {
                    float vx = c[2 * h], vy = c[2 * h + 1];
                    if (bias) { vx += bias[col]; vy += bias[col + 1]; }
                    if (t.outHalf) {
                        *(__half2*)((__half*)t.C + (size_t)gm * BN + col) =
                            __floats2half2_rn(vx, vy);
                    } else {
                        *(float2*)((float*)t.C + (size_t)gm * BN + col) =
                            make_float2(vx, vy);
                    }
                }
            }
        }
    }
}

// ------------------------------ gathers -------------------------------------
// accumulate mean of fp16 rows (D=128), 4-deep MLP
__device__ __forceinline__ void acc_rel128(int b, int e, int lane,
                                           const __half* __restrict__ y,
                                           float* res) {
    float acc[4] = {0.f, 0.f, 0.f, 0.f};
    int i = b;
    for (; i + 3 < e; i += 4) {
        #pragma unroll
        for (int k = 0; k < 4; k++) {
            const int s = __ldg(&g_src[i + k]);
            uint2 u = *(const uint2*)(y + (size_t)s * 128 + lane * 4);
            float2 a0 = __half22float2(*(const __half2*)&u.x);
            float2 a1 = __half22float2(*(const __half2*)&u.y);
            acc[0] += a0.x; acc[1] += a0.y; acc[2] += a1.x; acc[3] += a1.y;
        }
    }
    for (; i < e; i++) {
        const int s = __ldg(&g_src[i]);
        uint2 u = *(const uint2*)(y + (size_t)s * 128 + lane * 4);
        float2 a0 = __half22float2(*(const __half2*)&u.x);
        float2 a1 = __half22float2(*(const __half2*)&u.y);
        acc[0] += a0.x; acc[1] += a0.y; acc[2] += a1.x; acc[3] += a1.y;
    }
    const int deg = e - b;
    const float inv = deg > 0 ? 1.f / (float)deg : 0.f;
    #pragma unroll
    for (int v = 0; v < 4; v++) res[v] += acc[v] * inv;
}

// L1: papers -> hp1 = relu(S1p + meanW(yah) + meanC(yph)) as bf16 pair
//     authors -> ha1 = relu(S1a + meanA(yrh)) as bf16 pair
__global__ void gather_l1_kernel() {
    const int gw   = (blockIdx.x * blockDim.x + threadIdx.x) >> 5;
    const int lane = threadIdx.x & 31;
    float res[4] = {0.f, 0.f, 0.f, 0.f};
    const float* S;
    __nv_bfloat16 *oh, *ol;
    int node;
    if (gw < NPn) {
        node = gw;
        acc_rel128(g_off[gw], g_off[gw + 1], lane, g_yah, res);
        acc_rel128(g_off[NPn + gw], g_off[NPn + gw + 1], lane, g_yph, res);
        S = g_S1p; oh = g_hp1h; ol = g_hp1l;
    } else if (gw < NPn + NAn) {
        node = gw - NPn;
        acc_rel128(g_off[2 * NPn + node], g_off[2 * NPn + node + 1], lane, g_yrh, res);
        S = g_S1a; oh = g_ha1h; ol = g_ha1l;
    } else {
        return;
    }
    float4 s4 = *(const float4*)(S + (size_t)node * 128 + lane * 4);
    float v[4] = {fmaxf(s4.x + res[0], 0.f), fmaxf(s4.y + res[1], 0.f),
                  fmaxf(s4.z + res[2], 0.f), fmaxf(s4.w + res[3], 0.f)};
    __nv_bfloat16 hi[4], lo[4];
    #pragma unroll
    for (int k = 0; k < 4; k++) {
        hi[k] = __float2bfloat16(v[k]);
        lo[k] = __float2bfloat16(v[k] - __bfloat162float(hi[k]));
    }
    *(uint2*)(oh + (size_t)node * 128 + lane * 4) = *(uint2*)hi;
    *(uint2*)(ol + (size_t)node * 128 + lane * 4) = *(uint2*)lo;
}

// L2: papers -> out = S2 + meanW(zah) + meanC(zph)   (fp32, D=64)
__global__ void gather_l2_kernel(float* __restrict__ out) {
    const int gw   = (blockIdx.x * blockDim.x + threadIdx.x) >> 5;
    const int lane = threadIdx.x & 31;
    if (gw >= NPn) return;

    float res[2] = {0.f, 0.f};
    #pragma unroll
    for (int rel = 0; rel < 2; rel++) {
        const __half* y = rel ? g_zph : g_zah;
        const int b = g_off[rel * NPn + gw];
        const int e = g_off[rel * NPn + gw + 1];
        float acc0 = 0.f, acc1 = 0.f;
        int i = b;
        for (; i + 3 < e; i += 4) {
            #pragma unroll
            for (int k = 0; k < 4; k++) {
                const int s = __ldg(&g_src[i + k]);
                float2 a = __half22float2(*(const __half2*)(y + (size_t)s * 64 + lane * 2));
                acc0 += a.x; acc1 += a.y;
            }
        }
        for (; i < e; i++) {
            const int s = __ldg(&g_src[i]);
            float2 a = __half22float2(*(const __half2*)(y + (size_t)s * 64 + lane * 2));
            acc0 += a.x; acc1 += a.y;
        }
        const int deg = e - b;
        const float inv = deg > 0 ? 1.f / (float)deg : 0.f;
        res[0] += acc0 * inv;
        res[1] += acc1 * inv;
    }
    float2 s2 = *(const float2*)(g_S2 + (size_t)gw * 64 + lane * 2);
    *(float2*)(out + (size_t)gw * 64 + lane * 2) =
        make_float2(s2.x + res[0], s2.y + res[1]);
}

// ------------------------------- launch -------------------------------------
extern "C" void kernel_launch(void* const* d_in, const int* in_sizes, int n_in,
                              void* d_out, int out_size) {
    const float* xp  = (const float*)d_in[0];
    const float* xa  = (const float*)d_in[1];
    const float* Wl1 = (const float*)d_in[2];
    const float* bl1 = (const float*)d_in[3];
    const float* Wr1 = (const float*)d_in[4];
    const float* Wl2 = (const float*)d_in[5];
    const float* bl2 = (const float*)d_in[6];
    const float* Wr2 = (const float*)d_in[7];
    const int* wsrc = (const int*)d_in[8];
    const int* wdst = (const int*)d_in[9];
    const int* csrc = (const int*)d_in[10];
    const int* cdst = (const int*)d_in[11];
    const int* rsrc = (const int*)d_in[12];
    const int* rdst = (const int*)d_in[13];
    float* out = (float*)d_out;

    __half *p_yah, *p_yph, *p_yrh, *p_zah, *p_zph;
    float *p_S1p, *p_S1a, *p_S2, *p_Wc1, *p_bc1, *p_Wc2, *p_bc2;
    __nv_bfloat16 *p_hp1h, *p_hp1l, *p_ha1h, *p_ha1l;
    cudaGetSymbolAddress((void**)&p_yah, g_yah);
    cudaGetSymbolAddress((void**)&p_yph, g_yph);
    cudaGetSymbolAddress((void**)&p_yrh, g_yrh);
    cudaGetSymbolAddress((void**)&p_zah, g_zah);
    cudaGetSymbolAddress((void**)&p_zph, g_zph);
    cudaGetSymbolAddress((void**)&p_S1p, g_S1p);
    cudaGetSymbolAddress((void**)&p_S1a, g_S1a);
    cudaGetSymbolAddress((void**)&p_S2,  g_S2);
    cudaGetSymbolAddress((void**)&p_Wc1, g_Wc1);
    cudaGetSymbolAddress((void**)&p_bc1, g_bc1);
    cudaGetSymbolAddress((void**)&p_Wc2, g_Wc2);
    cudaGetSymbolAddress((void**)&p_bc2, g_bc2);
    cudaGetSymbolAddress((void**)&p_hp1h, g_hp1h);
    cudaGetSymbolAddress((void**)&p_hp1l, g_hp1l);
    cudaGetSymbolAddress((void**)&p_ha1h, g_ha1h);
    cudaGetSymbolAddress((void**)&p_ha1l, g_ha1l);

    constexpr int SMEM128 = (2 * 128 + 2 * 128) * 136 * 2;  // 139264
    constexpr int SMEM64  = (2 * 128 + 2 * 64) * 136 * 2;   // 104448
    cudaFuncSetAttribute((const void*)tc_mega<128>,
                         cudaFuncAttributeMaxDynamicSharedMemorySize, SMEM128);
    cudaFuncSetAttribute((const void*)tc_mega<64>,
                         cudaFuncAttributeMaxDynamicSharedMemorySize, SMEM64);

    const int gNP = (NPn + 127) / 128;   // 391
    const int gNA = (NAn + 127) / 128;   // 157

    // K1: zero deg + derived weights
    zero_prep_kernel<<<(NT + 255) / 256, 256>>>(Wr1, bl1, Wr2, bl2);

    // K2: L1 mega GEMM (ya|yp|yr|S1p|S1a) + hist CTAs
    {
        int e0 = HISTC + gNA;
        int e1 = e0 + gNP;
        int e2 = e1 + gNP;
        int e3 = e2 + gNP;
        int e4 = e3 + gNA;
        GTask ta = {xa, nullptr, Wl1 + 0 * DH * DIN, p_yah, nullptr, NAn, e0, 1, 0.5f};
        GTask tp = {xp, nullptr, Wl1 + 1 * DH * DIN, p_yph, nullptr, NPn, e1, 1, 0.5f};
        GTask tr = {xp, nullptr, Wl1 + 2 * DH * DIN, p_yrh, nullptr, NPn, e2, 1, 1.0f};
        GTask ts = {xp, nullptr, p_Wc1, p_S1p, p_bc1, NPn, e3, 0, 1.0f};
        GTask tu = {xa, nullptr, Wr1 + 2 * DH * DIN, p_S1a, bl1 + 2 * DH, NAn, e4, 0, 1.0f};
        tc_mega<128><<<e4, 256, SMEM128>>>(ta, tp, tr, ts, tu, HISTC,
                                           wsrc, wdst, csrc, cdst, rsrc, rdst);
    }

    // K3-K5: unified scan
    scan_bsum_kernel<<<NB, 256>>>();
    scan_base_kernel<<<1, 128>>>();
    scan_apply_kernel<<<NB, 256>>>();

    // K6: fill CSR
    fill_all_kernel<<<1024, 256>>>(wsrc, wdst, csrc, cdst, rsrc, rdst);

    // K7: L1 gather + relu + bf16-pair split (papers + authors)
    gather_l1_kernel<<<((NPn + NAn) * 32) / 256, 256>>>();

    // K8: L2 mega GEMM (za|zp|S2), A = bf16 pairs
    {
        int e0 = gNA;
        int e1 = e0 + gNP;
        int e2 = e1 + gNP;
        GTask ta = {p_ha1h, p_ha1l, Wl2 + 0 * DOUT * DH, p_zah, nullptr, NAn, e0, 1, 0.5f};
        GTask tp = {p_hp1h, p_hp1l, Wl2 + 1 * DOUT * DH, p_zph, nullptr, NPn, e1, 1, 0.5f};
        GTask ts = {p_hp1h, p_hp1l, p_Wc2, p_S2, p_bc2, NPn, e2, 0, 1.0f};
        tc_mega<64><<<e2, 256, SMEM64>>>(ta, tp, ts, ts, ts, 0,
                                         nullptr, nullptr, nullptr, nullptr,
                                         nullptr, nullptr);
    }

    // K9: L2 gather -> d_out
    gather_l2_kernel<<<(NPn * 32) / 256, 256>>>(out);
}

// round 8
// speedup vs baseline: 3.2014x; 1.1965x over previous
#include <cuda_runtime.h>
#include <cuda_bf16.h>
#include <cuda_fp16.h>
#include <cstdint>

// ---------------------------------------------------------------------------
// RSAGE_Hetero round 7:
//  - 512-thread GEMM CTAs (16 warps; 1 CTA/SM regime needs the extra warps)
//  - CSR build (hist+scan+fill) runs INSIDE the L1 mega-GEMM launch as 144
//    cooperating wave-1-resident "graph CTAs" with software barriers
//  - 5 launches total
// ---------------------------------------------------------------------------

constexpr int NPn  = 50000;
constexpr int NAn  = 20000;
constexpr int DIN  = 128;
constexpr int DH   = 128;
constexpr int DOUT = 64;
constexpr int EWn  = 250000;
constexpr int ECn  = 500000;
constexpr int ERn  = 250000;
constexpr int NT   = 2 * NPn + NAn;      // unified node slots (W|C|A) = 120000
constexpr int ET   = EWn + ECn + ERn;    // 1,000,000
constexpr int GC   = 144;                // graph CTAs (< 148 SMs: wave-1 resident)

// ------------------------------ scratch ------------------------------------
__device__ __half g_yah[NAn * DH];
__device__ __half g_yph[NPn * DH];
__device__ __half g_yrh[NPn * DH];
__device__ __half g_zah[NAn * DOUT];
__device__ __half g_zph[NPn * DOUT];
__device__ float  g_S1p[NPn * DH];
__device__ float  g_S1a[NAn * DH];
__device__ float  g_S2 [NPn * DOUT];
__device__ __nv_bfloat16 g_hp1h[NPn * DH], g_hp1l[NPn * DH];
__device__ __nv_bfloat16 g_ha1h[NAn * DH], g_ha1l[NAn * DH];

__device__ int g_deg[NT], g_off[NT + 1], g_cur[NT], g_src[ET];
__device__ int g_bsum[GC], g_bbase[GC];
__device__ int g_bar[4];                 // phase barrier counters

__device__ float g_Wc1[DH * DIN];
__device__ float g_bc1[DH];
__device__ float g_Wc2[DOUT * DH];
__device__ float g_bc2[DOUT];

// --------------------------- PTX helpers -----------------------------------
__device__ __forceinline__ uint32_t smem_u32(const void* p) {
    uint32_t a;
    asm("{ .reg .u64 t; cvta.to.shared.u64 t, %1; cvt.u32.u64 %0, t; }"
        : "=r"(a) : "l"(p));
    return a;
}

__device__ __forceinline__ void ldmx4(uint32_t* r, uint32_t addr) {
    asm volatile(
        "ldmatrix.sync.aligned.m8n8.x4.shared.b16 {%0,%1,%2,%3}, [%4];"
        : "=r"(r[0]), "=r"(r[1]), "=r"(r[2]), "=r"(r[3]) : "r"(addr));
}

__device__ __forceinline__ void mma16816(float* c, const uint32_t* a,
                                         uint32_t b0, uint32_t b1) {
    asm volatile(
        "mma.sync.aligned.m16n8k16.row.col.f32.bf16.bf16.f32 "
        "{%0,%1,%2,%3}, {%4,%5,%6,%7}, {%8,%9}, {%0,%1,%2,%3};"
        : "+f"(c[0]), "+f"(c[1]), "+f"(c[2]), "+f"(c[3])
        : "r"(a[0]), "r"(a[1]), "r"(a[2]), "r"(a[3]), "r"(b0), "r"(b1));
}

// software barrier among the GC graph CTAs (all wave-1 resident)
__device__ __forceinline__ void graph_bar(int idx) {
    __syncthreads();
    if (threadIdx.x == 0) {
        __threadfence();
        atomicAdd(&g_bar[idx], 1);
        while (*(volatile int*)&g_bar[idx] < GC) __nanosleep(64);
    }
    __syncthreads();
    __threadfence();
}

// --------------------------- setup -----------------------------------------
__global__ void zero_prep_kernel(const float* __restrict__ Wr1,
                                 const float* __restrict__ bl1,
                                 const float* __restrict__ Wr2,
                                 const float* __restrict__ bl2) {
    int i = blockIdx.x * blockDim.x + threadIdx.x;
    if (i < NT) g_deg[i] = 0;
    if (i < 4)  g_bar[i] = 0;
    if (i == 0) g_off[NT] = ET;
    if (i < DH * DIN)  g_Wc1[i] = 0.5f * (Wr1[i] + Wr1[DH * DIN + i]);
    if (i < DH)        g_bc1[i] = 0.5f * (bl1[i] + bl1[DH + i]);
    if (i < DOUT * DH) g_Wc2[i] = 0.5f * (Wr2[i] + Wr2[DOUT * DH + i]);
    if (i < DOUT)      g_bc2[i] = 0.5f * (bl2[i] + bl2[DOUT + i]);
}

// --------------------------- graph CTA program -------------------------------
__device__ void graph_cta(int c, char* smemRaw,
                          const int* wsrc, const int* wdst,
                          const int* csrc, const int* cdst,
                          const int* rsrc, const int* rdst) {
    int* s = (int*)smemRaw;                    // 512 ints
    const int tid = threadIdx.x;
    const int tg = c * 512 + tid;
    const int stride = GC * 512;

    // ---- phase A: histogram (int4-unrolled) ----
    for (int i = tg; i < EWn / 4; i += stride) {
        int4 d = ((const int4*)wdst)[i];
        atomicAdd(&g_deg[d.x], 1); atomicAdd(&g_deg[d.y], 1);
        atomicAdd(&g_deg[d.z], 1); atomicAdd(&g_deg[d.w], 1);
    }
    for (int i = tg; i < ECn / 4; i += stride) {
        int4 d = ((const int4*)cdst)[i];
        atomicAdd(&g_deg[NPn + d.x], 1); atomicAdd(&g_deg[NPn + d.y], 1);
        atomicAdd(&g_deg[NPn + d.z], 1); atomicAdd(&g_deg[NPn + d.w], 1);
    }
    for (int i = tg; i < ERn / 4; i += stride) {
        int4 d = ((const int4*)rdst)[i];
        atomicAdd(&g_deg[2 * NPn + d.x], 1); atomicAdd(&g_deg[2 * NPn + d.y], 1);
        atomicAdd(&g_deg[2 * NPn + d.z], 1); atomicAdd(&g_deg[2 * NPn + d.w], 1);
    }
    graph_bar(0);

    // ---- phase B1: per-CTA chunk scan (chunk = 1024 deg entries) ----
    const int i0 = c * 1024 + tid * 2;
    const int e0 = (i0 < NT) ? g_deg[i0] : 0;
    const int e1 = (i0 + 1 < NT) ? g_deg[i0 + 1] : 0;
    const int tsum = e0 + e1;
    s[tid] = tsum;
    __syncthreads();
    #pragma unroll
    for (int d = 1; d < 512; d <<= 1) {
        int v = (tid >= d) ? s[tid - d] : 0;
        __syncthreads();
        s[tid] += v;
        __syncthreads();
    }
    const int pre = s[tid] - tsum;             // exclusive within CTA
    if (tid == 511) g_bsum[c] = s[511];
    graph_bar(1);

    // ---- phase B2: CTA 0 scans the GC block sums ----
    if (c == 0) {
        int v = (tid < GC) ? g_bsum[tid] : 0;
        s[tid] = v;
        __syncthreads();
        #pragma unroll
        for (int d = 1; d < 512; d <<= 1) {
            int t = (tid >= d) ? s[tid - d] : 0;
            __syncthreads();
            s[tid] += t;
            __syncthreads();
        }
        if (tid < GC) g_bbase[tid] = s[tid] - v;
    }
    graph_bar(2);

    // ---- phase B3: write offsets ----
    {
        const int base = g_bbase[c] + pre;
        if (i0 < NT)     { g_off[i0] = base;          g_cur[i0] = base; }
        if (i0 + 1 < NT) { g_off[i0 + 1] = base + e0; g_cur[i0 + 1] = base + e0; }
    }
    graph_bar(3);

    // ---- phase C: fill ----
    for (int i = tg; i < EWn / 4; i += stride) {
        int4 d = ((const int4*)wdst)[i];
        int4 sv = ((const int4*)wsrc)[i];
        g_src[atomicAdd(&g_cur[d.x], 1)] = sv.x;
        g_src[atomicAdd(&g_cur[d.y], 1)] = sv.y;
        g_src[atomicAdd(&g_cur[d.z], 1)] = sv.z;
        g_src[atomicAdd(&g_cur[d.w], 1)] = sv.w;
    }
    for (int i = tg; i < ECn / 4; i += stride) {
        int4 d = ((const int4*)cdst)[i];
        int4 sv = ((const int4*)csrc)[i];
        g_src[atomicAdd(&g_cur[NPn + d.x], 1)] = sv.x;
        g_src[atomicAdd(&g_cur[NPn + d.y], 1)] = sv.y;
        g_src[atomicAdd(&g_cur[NPn + d.z], 1)] = sv.z;
        g_src[atomicAdd(&g_cur[NPn + d.w], 1)] = sv.w;
    }
    for (int i = tg; i < ERn / 4; i += stride) {
        int4 d = ((const int4*)rdst)[i];
        int4 sv = ((const int4*)rsrc)[i];
        g_src[atomicAdd(&g_cur[2 * NPn + d.x], 1)] = sv.x;
        g_src[atomicAdd(&g_cur[2 * NPn + d.y], 1)] = sv.y;
        g_src[atomicAdd(&g_cur[2 * NPn + d.z], 1)] = sv.z;
        g_src[atomicAdd(&g_cur[2 * NPn + d.w], 1)] = sv.w;
    }
}

// ---------------------- mma.sync split-bf16 mega GEMM -----------------------
struct GTask {
    const void* A;        // fp32 rows, or bf16 hi rows if Alo != null
    const void* Alo;      // bf16 lo rows
    const float* W;       // fp32 [BN,128]
    void* C;
    const float* bias;    // nullable
    int M;
    int ctaEnd;           // absolute (includes graph-CTA offset)
    int outHalf;
    float alpha;
};

template <int BN>
__global__ void __launch_bounds__(512, 1)
tc_mega(GTask t0, GTask t1, GTask t2, GTask t3, GTask t4, int gc,
        const int* wsrc, const int* wdst, const int* csrc, const int* cdst,
        const int* rsrc, const int* rdst) {
    constexpr int LDS = 136;
    constexpr int MT  = (BN == 128) ? 2 : 1;   // 16-row m tiles per warp
    constexpr int MW  = (BN == 128) ? 4 : 8;   // warps along m
    constexpr int NT_ = 4;                     // 8-col n tiles per warp (32 cols)

    extern __shared__ __align__(16) char smemRaw[];
    const int bId = blockIdx.x;

    if (bId < gc) {
        graph_cta(bId, smemRaw, wsrc, wdst, csrc, cdst, rsrc, rdst);
        return;
    }

    GTask t;
    int base;
    if (bId < t0.ctaEnd)      { t = t0; base = gc; }
    else if (bId < t1.ctaEnd) { t = t1; base = t0.ctaEnd; }
    else if (bId < t2.ctaEnd) { t = t2; base = t1.ctaEnd; }
    else if (bId < t3.ctaEnd) { t = t3; base = t2.ctaEnd; }
    else                      { t = t4; base = t3.ctaEnd; }

    const float* __restrict__ W    = t.W;
    const float* __restrict__ bias = t.bias;
    const int M = t.M;
    const float alpha = t.alpha;

    __nv_bfloat16* sm = (__nv_bfloat16*)smemRaw;
    __nv_bfloat16* sAhi = sm;
    __nv_bfloat16* sAlo = sAhi + 128 * LDS;
    __nv_bfloat16* sWhi = sAlo + 128 * LDS;
    __nv_bfloat16* sWlo = sWhi + BN * LDS;

    const int tid  = threadIdx.x;
    const int lane = tid & 31;
    const int wid  = tid >> 5;
    const int m0   = (bId - base) * 128;

    // ---- A tiles (512 threads: 32 rows/pass) ----
    const int cg = (tid & 15) * 8;
    if (t.Alo) {
        const __nv_bfloat16* Ah = (const __nv_bfloat16*)t.A;
        const __nv_bfloat16* Al = (const __nv_bfloat16*)t.Alo;
        #pragma unroll
        for (int r = tid >> 4; r < 128; r += 32) {
            const int gm = m0 + r;
            uint4 vh = make_uint4(0, 0, 0, 0), vl = vh;
            if (gm < M) {
                vh = *(const uint4*)(Ah + (size_t)gm * 128 + cg);
                vl = *(const uint4*)(Al + (size_t)gm * 128 + cg);
            }
            *(uint4*)(sAhi + r * LDS + cg) = vh;
            *(uint4*)(sAlo + r * LDS + cg) = vl;
        }
    } else {
        const float* A = (const float*)t.A;
        #pragma unroll
        for (int r = tid >> 4; r < 128; r += 32) {
            const int gm = m0 + r;
            float4 v0 = make_float4(0.f, 0.f, 0.f, 0.f), v1 = v0;
            if (gm < M) {
                const float4* p = (const float4*)(A + (size_t)gm * 128 + cg);
                v0 = p[0];
                v1 = p[1];
            }
            float f[8] = {v0.x, v0.y, v0.z, v0.w, v1.x, v1.y, v1.z, v1.w};
            __nv_bfloat16 hi[8], lo[8];
            #pragma unroll
            for (int i = 0; i < 8; i++) {
                hi[i] = __float2bfloat16(f[i]);
                lo[i] = __float2bfloat16(f[i] - __bfloat162float(hi[i]));
            }
            *(uint4*)(sAhi + r * LDS + cg) = *(uint4*)hi;
            *(uint4*)(sAlo + r * LDS + cg) = *(uint4*)lo;
        }
    }
    // ---- W tiles ----
    #pragma unroll
    for (int r = tid >> 4; r < BN; r += 32) {
        const float4* p = (const float4*)(W + (size_t)r * 128 + cg);
        float4 v0 = p[0];
        float4 v1 = p[1];
        float f[8] = {v0.x, v0.y, v0.z, v0.w, v1.x, v1.y, v1.z, v1.w};
        __nv_bfloat16 hi[8], lo[8];
        #pragma unroll
        for (int i = 0; i < 8; i++) {
            const float s = alpha * f[i];
            hi[i] = __float2bfloat16(s);
            lo[i] = __float2bfloat16(s - __bfloat162float(hi[i]));
        }
        *(uint4*)(sWhi + r * LDS + cg) = *(uint4*)hi;
        *(uint4*)(sWlo + r * LDS + cg) = *(uint4*)lo;
    }
    __syncthreads();

    // ---- warp-tiled mma mainloop: warp tile (MT*16) x 32 ----
    const int wm = (wid % MW) * (MT * 16);
    const int wn = (wid / MW) * 32;

    float acc[MT][NT_][4];
    #pragma unroll
    for (int mt = 0; mt < MT; mt++)
        #pragma unroll
        for (int nt = 0; nt < NT_; nt++)
            #pragma unroll
            for (int j = 0; j < 4; j++) acc[mt][nt][j] = 0.f;

    const uint32_t aAhi = smem_u32(sAhi);
    const uint32_t aAlo = smem_u32(sAlo);
    const uint32_t aWhi = smem_u32(sWhi);
    const uint32_t aWlo = smem_u32(sWlo);

    const int arow  = lane & 15;
    const int acol8 = (lane >> 4) * 8;
    const int brow  = (lane & 7) + ((lane >> 4) << 3);
    const int bcol8 = ((lane >> 3) & 1) * 8;

    #pragma unroll
    for (int k = 0; k < 8; k++) {
        const int kc = k * 16;
        uint32_t ahi[MT][4], alo[MT][4];
        #pragma unroll
        for (int mt = 0; mt < MT; mt++) {
            const uint32_t off =
                (uint32_t)((wm + mt * 16 + arow) * LDS + kc + acol8) * 2;
            ldmx4(ahi[mt], aAhi + off);
            ldmx4(alo[mt], aAlo + off);
        }
        #pragma unroll
        for (int np = 0; np < NT_ / 2; np++) {
            const uint32_t boff =
                (uint32_t)((wn + np * 16 + brow) * LDS + kc + bcol8) * 2;
            uint32_t bhi[4], blo[4];
            ldmx4(bhi, aWhi + boff);
            ldmx4(blo, aWlo + boff);
            #pragma unroll
            for (int mt = 0; mt < MT; mt++) {
                #pragma unroll
                for (int h = 0; h < 2; h++) {
                    float* c = acc[mt][np * 2 + h];
                    mma16816(c, ahi[mt], bhi[2 * h], bhi[2 * h + 1]);
                    mma16816(c, alo[mt], bhi[2 * h], bhi[2 * h + 1]);
                    mma16816(c, ahi[mt], blo[2 * h], blo[2 * h + 1]);
                }
            }
        }
    }

    // ---- epilogue ----
    #pragma unroll
    for (int mt = 0; mt < MT; mt++) {
        const int r0 = m0 + wm + mt * 16 + (lane >> 2);
        #pragma unroll
        for (int nt = 0; nt < NT_; nt++) {
            const int col = wn + nt * 8 + (lane & 3) * 2;
            const float* c = acc[mt][nt];
            #pragma unroll
            for (int h = 0; h < 2; h++) {
                const int gm = r0 + h * 8;
                if (gm < M) {
                    float vx = c[2 * h], vy = c[2 * h + 1];
                    if (bias) { vx += bias[col]; vy += bias[col + 1]; }
                    if (t.outHalf) {
                        *(__half2*)((__half*)t.C + (size_t)gm * BN + col) =
                            __floats2half2_rn(vx, vy);
                    } else {
                        *(float2*)((float*)t.C + (size_t)gm * BN + col) =
                            make_float2(vx, vy);
                    }
                }
            }
        }
    }
}

// ------------------------------ gathers -------------------------------------
__device__ __forceinline__ void acc_rel128(int b, int e, int lane,
                                           const __half* __restrict__ y,
                                           float* res) {
    float acc[4] = {0.f, 0.f, 0.f, 0.f};
    int i = b;
    for (; i + 3 < e; i += 4) {
        #pragma unroll
        for (int k = 0; k < 4; k++) {
            const int s = __ldg(&g_src[i + k]);
            uint2 u = *(const uint2*)(y + (size_t)s * 128 + lane * 4);
            float2 a0 = __half22float2(*(const __half2*)&u.x);
            float2 a1 = __half22float2(*(const __half2*)&u.y);
            acc[0] += a0.x; acc[1] += a0.y; acc[2] += a1.x; acc[3] += a1.y;
        }
    }
    for (; i < e; i++) {
        const int s = __ldg(&g_src[i]);
        uint2 u = *(const uint2*)(y + (size_t)s * 128 + lane * 4);
        float2 a0 = __half22float2(*(const __half2*)&u.x);
        float2 a1 = __half22float2(*(const __half2*)&u.y);
        acc[0] += a0.x; acc[1] += a0.y; acc[2] += a1.x; acc[3] += a1.y;
    }
    const int deg = e - b;
    const float inv = deg > 0 ? 1.f / (float)deg : 0.f;
    #pragma unroll
    for (int v = 0; v < 4; v++) res[v] += acc[v] * inv;
}

__global__ void gather_l1_kernel() {
    const int gw   = (blockIdx.x * blockDim.x + threadIdx.x) >> 5;
    const int lane = threadIdx.x & 31;
    float res[4] = {0.f, 0.f, 0.f, 0.f};
    const float* S;
    __nv_bfloat16 *oh, *ol;
    int node;
    if (gw < NPn) {
        node = gw;
        acc_rel128(g_off[gw], g_off[gw + 1], lane, g_yah, res);
        acc_rel128(g_off[NPn + gw], g_off[NPn + gw + 1], lane, g_yph, res);
        S = g_S1p; oh = g_hp1h; ol = g_hp1l;
    } else if (gw < NPn + NAn) {
        node = gw - NPn;
        acc_rel128(g_off[2 * NPn + node], g_off[2 * NPn + node + 1], lane, g_yrh, res);
        S = g_S1a; oh = g_ha1h; ol = g_ha1l;
    } else {
        return;
    }
    float4 s4 = *(const float4*)(S + (size_t)node * 128 + lane * 4);
    float v[4] = {fmaxf(s4.x + res[0], 0.f), fmaxf(s4.y + res[1], 0.f),
                  fmaxf(s4.z + res[2], 0.f), fmaxf(s4.w + res[3], 0.f)};
    __nv_bfloat16 hi[4], lo[4];
    #pragma unroll
    for (int k = 0; k < 4; k++) {
        hi[k] = __float2bfloat16(v[k]);
        lo[k] = __float2bfloat16(v[k] - __bfloat162float(hi[k]));
    }
    *(uint2*)(oh + (size_t)node * 128 + lane * 4) = *(uint2*)hi;
    *(uint2*)(ol + (size_t)node * 128 + lane * 4) = *(uint2*)lo;
}

__global__ void gather_l2_kernel(float* __restrict__ out) {
    const int gw   = (blockIdx.x * blockDim.x + threadIdx.x) >> 5;
    const int lane = threadIdx.x & 31;
    if (gw >= NPn) return;

    float res[2] = {0.f, 0.f};
    #pragma unroll
    for (int rel = 0; rel < 2; rel++) {
        const __half* y = rel ? g_zph : g_zah;
        const int b = g_off[rel * NPn + gw];
        const int e = g_off[rel * NPn + gw + 1];
        float acc0 = 0.f, acc1 = 0.f;
        int i = b;
        for (; i + 3 < e; i += 4) {
            #pragma unroll
            for (int k = 0; k < 4; k++) {
                const int s = __ldg(&g_src[i + k]);
                float2 a = __half22float2(*(const __half2*)(y + (size_t)s * 64 + lane * 2));
                acc0 += a.x; acc1 += a.y;
            }
        }
        for (; i < e; i++) {
            const int s = __ldg(&g_src[i]);
            float2 a = __half22float2(*(const __half2*)(y + (size_t)s * 64 + lane * 2));
            acc0 += a.x; acc1 += a.y;
        }
        const int deg = e - b;
        const float inv = deg > 0 ? 1.f / (float)deg : 0.f;
        res[0] += acc0 * inv;
        res[1] += acc1 * inv;
    }
    float2 s2 = *(const float2*)(g_S2 + (size_t)gw * 64 + lane * 2);
    *(float2*)(out + (size_t)gw * 64 + lane * 2) =
        make_float2(s2.x + res[0], s2.y + res[1]);
}

// ------------------------------- launch -------------------------------------
extern "C" void kernel_launch(void* const* d_in, const int* in_sizes, int n_in,
                              void* d_out, int out_size) {
    const float* xp  = (const float*)d_in[0];
    const float* xa  = (const float*)d_in[1];
    const float* Wl1 = (const float*)d_in[2];
    const float* bl1 = (const float*)d_in[3];
    const float* Wr1 = (const float*)d_in[4];
    const float* Wl2 = (const float*)d_in[5];
    const float* bl2 = (const float*)d_in[6];
    const float* Wr2 = (const float*)d_in[7];
    const int* wsrc = (const int*)d_in[8];
    const int* wdst = (const int*)d_in[9];
    const int* csrc = (const int*)d_in[10];
    const int* cdst = (const int*)d_in[11];
    const int* rsrc = (const int*)d_in[12];
    const int* rdst = (const int*)d_in[13];
    float* out = (float*)d_out;

    __half *p_yah, *p_yph, *p_yrh, *p_zah, *p_zph;
    float *p_S1p, *p_S1a, *p_S2, *p_Wc1, *p_bc1, *p_Wc2, *p_bc2;
    __nv_bfloat16 *p_hp1h, *p_hp1l, *p_ha1h, *p_ha1l;
    cudaGetSymbolAddress((void**)&p_yah, g_yah);
    cudaGetSymbolAddress((void**)&p_yph, g_yph);
    cudaGetSymbolAddress((void**)&p_yrh, g_yrh);
    cudaGetSymbolAddress((void**)&p_zah, g_zah);
    cudaGetSymbolAddress((void**)&p_zph, g_zph);
    cudaGetSymbolAddress((void**)&p_S1p, g_S1p);
    cudaGetSymbolAddress((void**)&p_S1a, g_S1a);
    cudaGetSymbolAddress((void**)&p_S2,  g_S2);
    cudaGetSymbolAddress((void**)&p_Wc1, g_Wc1);
    cudaGetSymbolAddress((void**)&p_bc1, g_bc1);
    cudaGetSymbolAddress((void**)&p_Wc2, g_Wc2);
    cudaGetSymbolAddress((void**)&p_bc2, g_bc2);
    cudaGetSymbolAddress((void**)&p_hp1h, g_hp1h);
    cudaGetSymbolAddress((void**)&p_hp1l, g_hp1l);
    cudaGetSymbolAddress((void**)&p_ha1h, g_ha1h);
    cudaGetSymbolAddress((void**)&p_ha1l, g_ha1l);

    constexpr int SMEM128 = (2 * 128 + 2 * 128) * 136 * 2;  // 139264
    constexpr int SMEM64  = (2 * 128 + 2 * 64) * 136 * 2;   // 104448
    cudaFuncSetAttribute((const void*)tc_mega<128>,
                         cudaFuncAttributeMaxDynamicSharedMemorySize, SMEM128);
    cudaFuncSetAttribute((const void*)tc_mega<64>,
                         cudaFuncAttributeMaxDynamicSharedMemorySize, SMEM64);

    const int gNP = (NPn + 127) / 128;   // 391
    const int gNA = (NAn + 127) / 128;   // 157

    // K1: zero deg/barriers + derived weights
    zero_prep_kernel<<<(NT + 255) / 256, 256>>>(Wr1, bl1, Wr2, bl2);

    // K2: graph CTAs (hist+scan+fill) + L1 mega GEMM (ya|yp|yr|S1p|S1a)
    {
        int e0 = GC + gNA;
        int e1 = e0 + gNP;
        int e2 = e1 + gNP;
        int e3 = e2 + gNP;
        int e4 = e3 + gNA;
        GTask ta = {xa, nullptr, Wl1 + 0 * DH * DIN, p_yah, nullptr, NAn, e0, 1, 0.5f};
        GTask tp = {xp, nullptr, Wl1 + 1 * DH * DIN, p_yph, nullptr, NPn, e1, 1, 0.5f};
        GTask tr = {xp, nullptr, Wl1 + 2 * DH * DIN, p_yrh, nullptr, NPn, e2, 1, 1.0f};
        GTask ts = {xp, nullptr, p_Wc1, p_S1p, p_bc1, NPn, e3, 0, 1.0f};
        GTask tu = {xa, nullptr, Wr1 + 2 * DH * DIN, p_S1a, bl1 + 2 * DH, NAn, e4, 0, 1.0f};
        tc_mega<128><<<e4, 512, SMEM128>>>(ta, tp, tr, ts, tu, GC,
                                           wsrc, wdst, csrc, cdst, rsrc, rdst);
    }

    // K3: L1 gather + relu + bf16-pair split
    gather_l1_kernel<<<((NPn + NAn) * 32) / 256, 256>>>();

    // K4: L2 mega GEMM (za|zp|S2), A = bf16 pairs
    {
        int e0 = gNA;
        int e1 = e0 + gNP;
        int e2 = e1 + gNP;
        GTask ta = {p_ha1h, p_ha1l, Wl2 + 0 * DOUT * DH, p_zah, nullptr, NAn, e0, 1, 0.5f};
        GTask tp = {p_hp1h, p_hp1l, Wl2 + 1 * DOUT * DH, p_zph, nullptr, NPn, e1, 1, 0.5f};
        GTask ts = {p_hp1h, p_hp1l, p_Wc2, p_S2, p_bc2, NPn, e2, 0, 1.0f};
        tc_mega<64><<<e2, 512, SMEM64>>>(ta, tp, ts, ts, ts, 0,
                                         nullptr, nullptr, nullptr, nullptr,
                                         nullptr, nullptr);
    }

    // K5: L2 gather -> d_out
    gather_l2_kernel<<<(NPn * 32) / 256, 256>>>(out);
}